// round 2
// baseline (speedup 1.0000x reference)
#include <cuda_runtime.h>
#include <math.h>

// Problem constants (fixed shapes)
#define BATCH  2
#define TSEQ   2048
#define DMODEL 1024
#define NHEADS 16
#define HDIM   64
#define BHTOT  (BATCH * NHEADS)     // 32
#define MROWS  (BATCH * TSEQ)       // 4096

// ---------------------------------------------------------------------------
// Scratch (static device globals; runtime allocation is forbidden)
// ---------------------------------------------------------------------------
__device__ float g_Q[BHTOT * TSEQ * HDIM];     // [B,H,T,Dh] 16 MB
__device__ float g_K[BHTOT * TSEQ * HDIM];
__device__ float g_V[BHTOT * TSEQ * HDIM];
__device__ float g_ctx[MROWS * DMODEL];        // [B,T,H*Dh] 16 MB

// ---------------------------------------------------------------------------
// GEMM: C[m,n] = sum_k A[m,k] * B[n,k] + bias[n]
// A: [M,K] row-major, B: [N,K] row-major (i.e. x @ W.T torch-Linear)
// out_mode 0: C row-major [M,N]
// out_mode 1: scatter to [B,H,T,Dh]:  C[((b*H+h)*T + t)*64 + d]
// Tiles: 128x128x16, 256 threads, 8x8 per-thread microtile.
// ---------------------------------------------------------------------------
#define GBM 128
#define GBN 128
#define GBK 16

__global__ __launch_bounds__(256) void gemm_nt_kernel(
    const float* __restrict__ A, const float* __restrict__ Bm,
    const float* __restrict__ bias, float* __restrict__ C,
    int M, int N, int K, int out_mode)
{
    __shared__ float As[GBK][GBM];
    __shared__ float Bs[GBK][GBN];

    const int tid = threadIdx.x;
    const int tx = tid & 15;          // n direction (16)
    const int ty = tid >> 4;          // m direction (16)
    const int m0 = blockIdx.y * GBM;
    const int n0 = blockIdx.x * GBN;

    float acc[8][8];
#pragma unroll
    for (int i = 0; i < 8; i++)
#pragma unroll
        for (int j = 0; j < 8; j++) acc[i][j] = 0.f;

    for (int k0 = 0; k0 < K; k0 += GBK) {
        // Load A tile (128x16) and B tile (128x16) as float4, transpose into smem
#pragma unroll
        for (int it = 0; it < 2; it++) {
            int flat = tid + it * 256;          // 0..511
            int r  = flat >> 2;                 // 0..127
            int c4 = flat & 3;                  // 0..3 (float4 within row)
            float4 a = *(const float4*)&A[(size_t)(m0 + r) * K + k0 + c4 * 4];
            As[c4 * 4 + 0][r] = a.x; As[c4 * 4 + 1][r] = a.y;
            As[c4 * 4 + 2][r] = a.z; As[c4 * 4 + 3][r] = a.w;
            float4 b = *(const float4*)&Bm[(size_t)(n0 + r) * K + k0 + c4 * 4];
            Bs[c4 * 4 + 0][r] = b.x; Bs[c4 * 4 + 1][r] = b.y;
            Bs[c4 * 4 + 2][r] = b.z; Bs[c4 * 4 + 3][r] = b.w;
        }
        __syncthreads();

#pragma unroll
        for (int kk = 0; kk < GBK; kk++) {
            float4 a0 = *(const float4*)&As[kk][ty * 8];
            float4 a1 = *(const float4*)&As[kk][ty * 8 + 4];
            float4 b0 = *(const float4*)&Bs[kk][tx * 8];
            float4 b1 = *(const float4*)&Bs[kk][tx * 8 + 4];
            float ra[8] = {a0.x, a0.y, a0.z, a0.w, a1.x, a1.y, a1.z, a1.w};
            float rb[8] = {b0.x, b0.y, b0.z, b0.w, b1.x, b1.y, b1.z, b1.w};
#pragma unroll
            for (int i = 0; i < 8; i++)
#pragma unroll
                for (int j = 0; j < 8; j++)
                    acc[i][j] += ra[i] * rb[j];
        }
        __syncthreads();
    }

    // Epilogue
#pragma unroll
    for (int i = 0; i < 8; i++) {
        int m = m0 + ty * 8 + i;
#pragma unroll
        for (int j = 0; j < 8; j++) {
            int n = n0 + tx * 8 + j;
            float v = acc[i][j] + bias[n];
            if (out_mode == 0) {
                C[(size_t)m * N + n] = v;
            } else {
                int b = m >> 11;            // / TSEQ
                int t = m & (TSEQ - 1);
                int h = n >> 6;             // / HDIM
                int d = n & (HDIM - 1);
                C[(((size_t)(b * NHEADS + h)) * TSEQ + t) * HDIM + d] = v;
            }
        }
    }
}

// ---------------------------------------------------------------------------
// RoPE: rotate Q and K in place. Layout [BH, T, 64].
// q'[d]    = q[d]*cos - q[d+32]*sin
// q'[d+32] = q[d+32]*cos + q[d]*sin,   angle = t * 10000^{-d/32}
// ---------------------------------------------------------------------------
__global__ void rope_kernel(float* __restrict__ Q, float* __restrict__ K)
{
    int idx = blockIdx.x * blockDim.x + threadIdx.x;
    if (idx >= BHTOT * TSEQ * 32) return;
    int d  = idx & 31;
    int t  = (idx >> 5) & (TSEQ - 1);
    int bh = idx >> 16;                 // / (TSEQ*32)

    float inv_freq = powf(10000.f, -(float)d * (1.f / 32.f));
    float ang = (float)t * inv_freq;
    float s, c;
    sincosf(ang, &s, &c);

    size_t base = ((size_t)bh * TSEQ + t) * HDIM;
    float q1 = Q[base + d], q2 = Q[base + d + 32];
    Q[base + d]      = q1 * c - q2 * s;
    Q[base + d + 32] = q2 * c + q1 * s;
    float k1 = K[base + d], k2 = K[base + d + 32];
    K[base + d]      = k1 * c - k2 * s;
    K[base + d + 32] = k2 * c + k1 * s;
}

// ---------------------------------------------------------------------------
// Flash attention (fp32). One thread = one query row; 128 rows per block.
// KV tiles of 32 keys in smem. Online softmax. Output -> ctx [B,T,H*Dh].
// ---------------------------------------------------------------------------
#define ABM 128
#define ABN 32

__global__ __launch_bounds__(ABM) void attn_kernel(
    const float* __restrict__ Q, const float* __restrict__ K,
    const float* __restrict__ V, float* __restrict__ ctx)
{
    __shared__ float Ks[ABN][HDIM];
    __shared__ float Vs[ABN][HDIM];
    __shared__ float Ss[ABM][ABN];      // per-row scores, bank-swizzled

    const int tid = threadIdx.x;
    const int bh  = blockIdx.y;
    const int row = blockIdx.x * ABM + tid;     // query index in [0,T)
    const int sw  = tid & 31;                   // swizzle key

    const float* qptr = Q + ((size_t)bh * TSEQ + row) * HDIM;
    float4 q[16];
#pragma unroll
    for (int i = 0; i < 16; i++) q[i] = ((const float4*)qptr)[i];

    float4 o[16];
#pragma unroll
    for (int i = 0; i < 16; i++) o[i] = make_float4(0.f, 0.f, 0.f, 0.f);
    float mrow = -INFINITY, lsum = 0.f;

    for (int kt = 0; kt < TSEQ; kt += ABN) {
        // load K,V tile: 32x64 floats each = 512 float4 each; 4 per thread
#pragma unroll
        for (int it = 0; it < 4; it++) {
            int flat = tid + it * 128;       // 0..511
            int r = flat >> 4;               // 16 float4 per row
            int c = flat & 15;
            ((float4*)&Ks[r][0])[c] =
                ((const float4*)&K[((size_t)bh * TSEQ + kt + r) * HDIM])[c];
            ((float4*)&Vs[r][0])[c] =
                ((const float4*)&V[((size_t)bh * TSEQ + kt + r) * HDIM])[c];
        }
        __syncthreads();

        // scores for my row vs this key tile
        float tmax = mrow;
#pragma unroll 4
        for (int j = 0; j < ABN; j++) {
            float s0 = 0.f, s1 = 0.f, s2 = 0.f, s3 = 0.f;
#pragma unroll
            for (int i = 0; i < 16; i++) {
                float4 kv = ((const float4*)&Ks[j][0])[i];   // warp broadcast
                s0 += q[i].x * kv.x; s1 += q[i].y * kv.y;
                s2 += q[i].z * kv.z; s3 += q[i].w * kv.w;
            }
            float s = ((s0 + s1) + (s2 + s3)) * 0.125f;      // 1/sqrt(64)
            tmax = fmaxf(tmax, s);
            Ss[tid][j ^ sw] = s;
        }

        // rescale and accumulate
        float corr = __expf(mrow - tmax);    // first tile: exp(-inf)=0
        mrow = tmax;
        lsum *= corr;
#pragma unroll
        for (int i = 0; i < 16; i++) {
            o[i].x *= corr; o[i].y *= corr; o[i].z *= corr; o[i].w *= corr;
        }
#pragma unroll 4
        for (int j = 0; j < ABN; j++) {
            float p = __expf(Ss[tid][j ^ sw] - mrow);
            lsum += p;
#pragma unroll
            for (int i = 0; i < 16; i++) {
                float4 vv = ((const float4*)&Vs[j][0])[i];   // warp broadcast
                o[i].x += p * vv.x; o[i].y += p * vv.y;
                o[i].z += p * vv.z; o[i].w += p * vv.w;
            }
        }
        __syncthreads();
    }

    float inv = 1.f / lsum;
    // ctx layout [B,T,H,Dh]: ((b*T + t)*H + h)*64 + d
    int b = bh >> 4, h = bh & 15;
    float* optr = g_ctx + (((size_t)b * TSEQ + row) * NHEADS + h) * HDIM;
#pragma unroll
    for (int i = 0; i < 16; i++) {
        float4 v = o[i];
        v.x *= inv; v.y *= inv; v.z *= inv; v.w *= inv;
        ((float4*)optr)[i] = v;
    }
    (void)ctx;
}

// ---------------------------------------------------------------------------
// Launch
// ---------------------------------------------------------------------------
extern "C" void kernel_launch(void* const* d_in, const int* in_sizes, int n_in,
                              void* d_out, int out_size)
{
    const float* x  = (const float*)d_in[0];
    const float* Wq = (const float*)d_in[1];
    const float* bq = (const float*)d_in[2];
    const float* Wk = (const float*)d_in[3];
    const float* bk = (const float*)d_in[4];
    const float* Wv = (const float*)d_in[5];
    const float* bv = (const float*)d_in[6];
    const float* Wo = (const float*)d_in[7];
    const float* bo = (const float*)d_in[8];
    float* out = (float*)d_out;

    float *Qp, *Kp, *Vp, *Cp;
    cudaGetSymbolAddress((void**)&Qp, g_Q);
    cudaGetSymbolAddress((void**)&Kp, g_K);
    cudaGetSymbolAddress((void**)&Vp, g_V);
    cudaGetSymbolAddress((void**)&Cp, g_ctx);

    dim3 ggrid(DMODEL / GBN, MROWS / GBM);   // (8, 32)
    // QKV projections -> [B,H,T,Dh]
    gemm_nt_kernel<<<ggrid, 256>>>(x, Wq, bq, Qp, MROWS, DMODEL, DMODEL, 1);
    gemm_nt_kernel<<<ggrid, 256>>>(x, Wk, bk, Kp, MROWS, DMODEL, DMODEL, 1);
    gemm_nt_kernel<<<ggrid, 256>>>(x, Wv, bv, Vp, MROWS, DMODEL, DMODEL, 1);

    // RoPE on Q,K
    int nrope = BHTOT * TSEQ * 32;
    rope_kernel<<<(nrope + 255) / 256, 256>>>(Qp, Kp);

    // Attention -> ctx
    dim3 agrid(TSEQ / ABM, BHTOT);           // (16, 32)
    attn_kernel<<<agrid, ABM>>>(Qp, Kp, Vp, Cp);

    // Output projection -> d_out (row-major [B*T, D])
    gemm_nt_kernel<<<ggrid, 256>>>(Cp, Wo, bo, out, MROWS, DMODEL, DMODEL, 0);

    (void)in_sizes; (void)n_in; (void)out_size;
}

// round 4
// speedup vs baseline: 1.3782x; 1.3782x over previous
#include <cuda_runtime.h>
#include <cuda_bf16.h>
#include <math.h>
#include <stdint.h>

// Problem constants
#define BATCH  2
#define TSEQ   2048
#define DMODEL 1024
#define NHEADS 16
#define HDIM   64
#define BHTOT  (BATCH * NHEADS)     // 32
#define MROWS  (BATCH * TSEQ)       // 4096
#define KSPLIT 3072                 // split-bf16 3-term K

// ---------------------------------------------------------------------------
// Scratch
// ---------------------------------------------------------------------------
__device__ float g_Q[BHTOT * TSEQ * HDIM];     // [B,H,T,Dh]
__device__ float g_K[BHTOT * TSEQ * HDIM];
__device__ float g_V[BHTOT * TSEQ * HDIM];
__device__ float g_ctx[MROWS * DMODEL];        // [B,T,H*Dh]
__device__ __nv_bfloat16 g_A2[(size_t)MROWS * KSPLIT];    // split activations
__device__ __nv_bfloat16 g_Bqkv[(size_t)3072 * KSPLIT];   // split Wq|Wk|Wv
__device__ __nv_bfloat16 g_Bo[(size_t)1024 * KSPLIT];     // split Wo
__device__ float g_bias_qkv[3072];

// ---------------------------------------------------------------------------
// Helpers (baseline ISA only: cp.async + ldmatrix + mma.sync)
// ---------------------------------------------------------------------------
__device__ __forceinline__ uint32_t smem_u32(const void* p) {
    uint32_t a;
    asm("{ .reg .u64 t; cvta.to.shared.u64 t, %1; cvt.u32.u64 %0, t; }"
        : "=r"(a) : "l"(p));
    return a;
}

#define CP_ASYNC16(sm, gp) \
    asm volatile("cp.async.cg.shared.global [%0], [%1], 16;" :: "r"((uint32_t)(sm)), "l"(gp) : "memory")
#define CP_COMMIT() asm volatile("cp.async.commit_group;" ::: "memory")
#define CP_WAIT(n)  asm volatile("cp.async.wait_group %0;" :: "n"(n) : "memory")

__device__ __forceinline__ void ldsm4(uint32_t* r, uint32_t addr) {
    asm volatile("ldmatrix.sync.aligned.m8n8.x4.shared.b16 {%0,%1,%2,%3}, [%4];"
        : "=r"(r[0]), "=r"(r[1]), "=r"(r[2]), "=r"(r[3]) : "r"(addr));
}

__device__ __forceinline__ void mma_bf16(float* c, const uint32_t* a, const uint32_t* b) {
    asm volatile(
        "mma.sync.aligned.m16n8k16.row.col.f32.bf16.bf16.f32 "
        "{%0,%1,%2,%3}, {%4,%5,%6,%7}, {%8,%9}, {%0,%1,%2,%3};"
        : "+f"(c[0]), "+f"(c[1]), "+f"(c[2]), "+f"(c[3])
        : "r"(a[0]), "r"(a[1]), "r"(a[2]), "r"(a[3]), "r"(b[0]), "r"(b[1]));
}

// 16B-chunk swizzle for 64B rows (32 bf16): conflict-free ldmatrix + cp.async
__device__ __forceinline__ uint32_t swz(int row, int chunk) {
    return (uint32_t)(row * 64 + ((chunk ^ ((row >> 1) & 3)) << 4));
}

// ---------------------------------------------------------------------------
// Split fp32 -> bf16 3-term layout.
// a-side (bside=0): [hi | lo | hi] ; b-side (bside=1): [hi | hi | lo]
// ---------------------------------------------------------------------------
__global__ void split_kernel(const float* __restrict__ src,
                             __nv_bfloat16* __restrict__ dst, int bside)
{
    int idx = blockIdx.x * blockDim.x + threadIdx.x;
    int r = idx >> 10, k = idx & 1023;
    float v = src[idx];
    __nv_bfloat16 hi = __float2bfloat16(v);
    __nv_bfloat16 lo = __float2bfloat16(v - __bfloat162float(hi));
    size_t base = (size_t)r * KSPLIT;
    dst[base + k] = hi;
    dst[base + 1024 + k] = bside ? hi : lo;
    dst[base + 2048 + k] = bside ? lo : hi;
}

__global__ void bias_concat_kernel(const float* __restrict__ bq,
                                   const float* __restrict__ bk,
                                   const float* __restrict__ bv)
{
    int i = blockIdx.x * blockDim.x + threadIdx.x;   // 3072 total
    const float* s = (i < 1024) ? bq : ((i < 2048) ? bk : bv);
    g_bias_qkv[i] = s[i & 1023];
}

// ---------------------------------------------------------------------------
// HMMA bf16 GEMM: C[m,n] = sum_k A2[m,k]*B2[n,k] + bias[n],  K = 3072
// CTA 128x128, BK=32, 8 warps (4m x 2n), warp tile 32x64.
// cp.async double-buffered smem, swizzled; ldmatrix x4 fragments.
// mode 0: row-major out. mode 1: scatter QKV to [B,H,T,Dh].
// ---------------------------------------------------------------------------
#define GK KSPLIT
#define NS (GK / 32)      // 96 stages

__global__ __launch_bounds__(256) void gemm_hmma(
    const __nv_bfloat16* __restrict__ A2, const __nv_bfloat16* __restrict__ B2,
    const float* __restrict__ bias, float* __restrict__ out0,
    float* __restrict__ outQ, float* __restrict__ outK, float* __restrict__ outV,
    int mode)
{
    __shared__ __align__(128) char sA[2][128 * 64];   // 128 rows x 32 bf16
    __shared__ __align__(128) char sB[2][128 * 64];

    const int tid = threadIdx.x;
    const int lane = tid & 31;
    const int wid = tid >> 5;
    const int warp_m = wid & 3;       // 0..3
    const int warp_n = wid >> 2;      // 0..1
    const int m0 = blockIdx.y * 128;
    const int n0 = blockIdx.x * 128;

    const uint32_t sbA[2] = { smem_u32(sA[0]), smem_u32(sA[1]) };
    const uint32_t sbB[2] = { smem_u32(sB[0]), smem_u32(sB[1]) };

    const __nv_bfloat16* Abase = A2 + (size_t)m0 * GK;
    const __nv_bfloat16* Bbase = B2 + (size_t)n0 * GK;

    float acc[2][8][4];
#pragma unroll
    for (int i = 0; i < 2; i++)
#pragma unroll
        for (int j = 0; j < 8; j++)
#pragma unroll
            for (int q = 0; q < 4; q++) acc[i][j][q] = 0.f;

    // stage loader: 128 rows x 4 chunks (16B) for A and B
    auto load_stage = [&](int s) {
        int b = s & 1;
        const __nv_bfloat16* Ag = Abase + s * 32;
        const __nv_bfloat16* Bg = Bbase + s * 32;
#pragma unroll
        for (int u = 0; u < 2; u++) {
            int flat = tid + u * 256;            // 0..511
            int r = flat >> 2, c8 = flat & 3;
            uint32_t off = swz(r, c8);
            CP_ASYNC16(sbA[b] + off, (const void*)(Ag + (size_t)r * GK + c8 * 8));
            CP_ASYNC16(sbB[b] + off, (const void*)(Bg + (size_t)r * GK + c8 * 8));
        }
        CP_COMMIT();
    };

    load_stage(0);

    for (int s = 0; s < NS; s++) {
        int b = s & 1;
        if (s + 1 < NS) {
            load_stage(s + 1);
            CP_WAIT(1);
        } else {
            CP_WAIT(0);
        }
        __syncthreads();

#pragma unroll
        for (int kk = 0; kk < 2; kk++) {
            // A fragments: 2 m16 tiles
            uint32_t af[2][4];
#pragma unroll
            for (int tm = 0; tm < 2; tm++) {
                int row = warp_m * 32 + tm * 16 + (lane & 7) + ((lane >> 3) & 1) * 8;
                int chunk = kk * 2 + (lane >> 4);
                ldsm4(af[tm], sbA[b] + swz(row, chunk));
            }
            // B fragments: 4 pairs of n8 tiles
            uint32_t bf[4][4];
#pragma unroll
            for (int p = 0; p < 4; p++) {
                int row = warp_n * 64 + p * 16 + (lane & 7) + (lane >> 4) * 8;
                int chunk = kk * 2 + ((lane >> 3) & 1);
                ldsm4(bf[p], sbB[b] + swz(row, chunk));
            }
#pragma unroll
            for (int tm = 0; tm < 2; tm++)
#pragma unroll
                for (int tn = 0; tn < 8; tn++) {
                    const uint32_t* bb = &bf[tn >> 1][(tn & 1) * 2];
                    mma_bf16(acc[tm][tn], af[tm], bb);
                }
        }
        __syncthreads();
    }

    // Epilogue
    const int m_base = m0 + warp_m * 32;
    const int n_base = n0 + warp_n * 64;
#pragma unroll
    for (int tm = 0; tm < 2; tm++) {
#pragma unroll
        for (int tn = 0; tn < 8; tn++) {
            int r0 = m_base + tm * 16 + (lane >> 2);
            int c0 = n_base + tn * 8 + 2 * (lane & 3);
            float bx = bias[c0], by = bias[c0 + 1];
#pragma unroll
            for (int half = 0; half < 2; half++) {
                int m = r0 + half * 8;
                float vx = acc[tm][tn][half * 2 + 0] + bx;
                float vy = acc[tm][tn][half * 2 + 1] + by;
                if (mode == 0) {
                    float2* dst = (float2*)(out0 + (size_t)m * 1024 + c0);
                    *dst = make_float2(vx, vy);
                } else {
                    int which = c0 >> 10;
                    int nn = c0 & 1023;
                    int head = nn >> 6;
                    int d0 = nn & 63;
                    int bb2 = m >> 11;
                    int t = m & (TSEQ - 1);
                    float* P = (which == 0) ? outQ : ((which == 1) ? outK : outV);
                    float2* dst = (float2*)(P +
                        (((size_t)(bb2 * NHEADS + head)) * TSEQ + t) * HDIM + d0);
                    *dst = make_float2(vx, vy);
                }
            }
        }
    }
}

// ---------------------------------------------------------------------------
// RoPE (unchanged)
// ---------------------------------------------------------------------------
__global__ void rope_kernel(float* __restrict__ Q, float* __restrict__ K)
{
    int idx = blockIdx.x * blockDim.x + threadIdx.x;
    if (idx >= BHTOT * TSEQ * 32) return;
    int d  = idx & 31;
    int t  = (idx >> 5) & (TSEQ - 1);
    int bh = idx >> 16;

    float inv_freq = powf(10000.f, -(float)d * (1.f / 32.f));
    float ang = (float)t * inv_freq;
    float s, c;
    sincosf(ang, &s, &c);

    size_t base = ((size_t)bh * TSEQ + t) * HDIM;
    float q1 = Q[base + d], q2 = Q[base + d + 32];
    Q[base + d]      = q1 * c - q2 * s;
    Q[base + d + 32] = q2 * c + q1 * s;
    float k1 = K[base + d], k2 = K[base + d + 32];
    K[base + d]      = k1 * c - k2 * s;
    K[base + d + 32] = k2 * c + k1 * s;
}

// ---------------------------------------------------------------------------
// Flash attention fp32 (unchanged from R1 — correct baseline)
// ---------------------------------------------------------------------------
#define ABM 128
#define ABN 32

__global__ __launch_bounds__(ABM) void attn_kernel(
    const float* __restrict__ Q, const float* __restrict__ K,
    const float* __restrict__ V, float* __restrict__ ctx)
{
    __shared__ float Ks[ABN][HDIM];
    __shared__ float Vs[ABN][HDIM];
    __shared__ float Ss[ABM][ABN];

    const int tid = threadIdx.x;
    const int bh  = blockIdx.y;
    const int row = blockIdx.x * ABM + tid;
    const int sw  = tid & 31;

    const float* qptr = Q + ((size_t)bh * TSEQ + row) * HDIM;
    float4 q[16];
#pragma unroll
    for (int i = 0; i < 16; i++) q[i] = ((const float4*)qptr)[i];

    float4 o[16];
#pragma unroll
    for (int i = 0; i < 16; i++) o[i] = make_float4(0.f, 0.f, 0.f, 0.f);
    float mrow = -INFINITY, lsum = 0.f;

    for (int kt = 0; kt < TSEQ; kt += ABN) {
#pragma unroll
        for (int it = 0; it < 4; it++) {
            int flat = tid + it * 128;
            int r = flat >> 4;
            int c = flat & 15;
            ((float4*)&Ks[r][0])[c] =
                ((const float4*)&K[((size_t)bh * TSEQ + kt + r) * HDIM])[c];
            ((float4*)&Vs[r][0])[c] =
                ((const float4*)&V[((size_t)bh * TSEQ + kt + r) * HDIM])[c];
        }
        __syncthreads();

        float tmax = mrow;
#pragma unroll 4
        for (int j = 0; j < ABN; j++) {
            float s0 = 0.f, s1 = 0.f, s2 = 0.f, s3 = 0.f;
#pragma unroll
            for (int i = 0; i < 16; i++) {
                float4 kv = ((const float4*)&Ks[j][0])[i];
                s0 += q[i].x * kv.x; s1 += q[i].y * kv.y;
                s2 += q[i].z * kv.z; s3 += q[i].w * kv.w;
            }
            float s = ((s0 + s1) + (s2 + s3)) * 0.125f;
            tmax = fmaxf(tmax, s);
            Ss[tid][j ^ sw] = s;
        }

        float corr = __expf(mrow - tmax);
        mrow = tmax;
        lsum *= corr;
#pragma unroll
        for (int i = 0; i < 16; i++) {
            o[i].x *= corr; o[i].y *= corr; o[i].z *= corr; o[i].w *= corr;
        }
#pragma unroll 4
        for (int j = 0; j < ABN; j++) {
            float p = __expf(Ss[tid][j ^ sw] - mrow);
            lsum += p;
#pragma unroll
            for (int i = 0; i < 16; i++) {
                float4 vv = ((const float4*)&Vs[j][0])[i];
                o[i].x += p * vv.x; o[i].y += p * vv.y;
                o[i].z += p * vv.z; o[i].w += p * vv.w;
            }
        }
        __syncthreads();
    }

    float inv = 1.f / lsum;
    int b = bh >> 4, h = bh & 15;
    float* optr = ctx + (((size_t)b * TSEQ + row) * NHEADS + h) * HDIM;
#pragma unroll
    for (int i = 0; i < 16; i++) {
        float4 v = o[i];
        v.x *= inv; v.y *= inv; v.z *= inv; v.w *= inv;
        ((float4*)optr)[i] = v;
    }
}

// ---------------------------------------------------------------------------
// Launch
// ---------------------------------------------------------------------------
extern "C" void kernel_launch(void* const* d_in, const int* in_sizes, int n_in,
                              void* d_out, int out_size)
{
    const float* x  = (const float*)d_in[0];
    const float* Wq = (const float*)d_in[1];
    const float* bq = (const float*)d_in[2];
    const float* Wk = (const float*)d_in[3];
    const float* bk = (const float*)d_in[4];
    const float* Wv = (const float*)d_in[5];
    const float* bv = (const float*)d_in[6];
    const float* Wo = (const float*)d_in[7];
    const float* bo = (const float*)d_in[8];
    float* out = (float*)d_out;

    float *Qp, *Kp, *Vp, *Cp, *BIp;
    __nv_bfloat16 *A2p, *Bqkvp, *Bop;
    cudaGetSymbolAddress((void**)&Qp, g_Q);
    cudaGetSymbolAddress((void**)&Kp, g_K);
    cudaGetSymbolAddress((void**)&Vp, g_V);
    cudaGetSymbolAddress((void**)&Cp, g_ctx);
    cudaGetSymbolAddress((void**)&A2p, g_A2);
    cudaGetSymbolAddress((void**)&Bqkvp, g_Bqkv);
    cudaGetSymbolAddress((void**)&Bop, g_Bo);
    cudaGetSymbolAddress((void**)&BIp, g_bias_qkv);

    // split conversions
    split_kernel<<<(MROWS * 1024) / 256, 256>>>(x, A2p, 0);
    split_kernel<<<(1024 * 1024) / 256, 256>>>(Wq, Bqkvp + (size_t)0 * 1024 * KSPLIT, 1);
    split_kernel<<<(1024 * 1024) / 256, 256>>>(Wk, Bqkvp + (size_t)1 * 1024 * KSPLIT, 1);
    split_kernel<<<(1024 * 1024) / 256, 256>>>(Wv, Bqkvp + (size_t)2 * 1024 * KSPLIT, 1);
    split_kernel<<<(1024 * 1024) / 256, 256>>>(Wo, Bop, 1);
    bias_concat_kernel<<<12, 256>>>(bq, bk, bv);

    // fused QKV projection (HMMA tensor cores) -> [B,H,T,Dh]
    gemm_hmma<<<dim3(3072 / 128, MROWS / 128), 256>>>(
        A2p, Bqkvp, BIp, nullptr, Qp, Kp, Vp, 1);

    // RoPE
    rope_kernel<<<(BHTOT * TSEQ * 32 + 255) / 256, 256>>>(Qp, Kp);

    // attention -> ctx
    attn_kernel<<<dim3(TSEQ / ABM, BHTOT), ABM>>>(Qp, Kp, Vp, Cp);

    // ctx split + output projection -> d_out
    split_kernel<<<(MROWS * 1024) / 256, 256>>>(Cp, A2p, 0);
    gemm_hmma<<<dim3(1024 / 128, MROWS / 128), 256>>>(
        A2p, Bop, bo, out, nullptr, nullptr, nullptr, 0);

    (void)in_sizes; (void)n_in; (void)out_size;
}

// round 5
// speedup vs baseline: 3.1234x; 2.2662x over previous
#include <cuda_runtime.h>
#include <cuda_bf16.h>
#include <math.h>
#include <stdint.h>

// Problem constants
#define BATCH  2
#define TSEQ   2048
#define DMODEL 1024
#define NHEADS 16
#define HDIM   64
#define BHTOT  (BATCH * NHEADS)     // 32
#define MROWS  (BATCH * TSEQ)       // 4096
#define KSPLIT 3072                 // split-bf16 3-term K

// ---------------------------------------------------------------------------
// Scratch
// ---------------------------------------------------------------------------
__device__ float g_Q[BHTOT * TSEQ * HDIM];     // [B,H,T,Dh] fp32 (pre-rope)
__device__ float g_K[BHTOT * TSEQ * HDIM];
__device__ float g_V[BHTOT * TSEQ * HDIM];
__device__ __nv_bfloat16 g_Qh[(size_t)BHTOT * TSEQ * 128];  // [bh][t][hi64|lo64]
__device__ __nv_bfloat16 g_Kh[(size_t)BHTOT * TSEQ * 128];
__device__ __nv_bfloat16 g_Vt[(size_t)BHTOT * 128 * TSEQ];  // [bh][d'128][t]
__device__ __nv_bfloat16 g_A2[(size_t)MROWS * KSPLIT];    // split activations
__device__ __nv_bfloat16 g_Bqkv[(size_t)3072 * KSPLIT];   // split Wq|Wk|Wv
__device__ __nv_bfloat16 g_Bo[(size_t)1024 * KSPLIT];     // split Wo
__device__ float g_bias_qkv[3072];

// ---------------------------------------------------------------------------
// Helpers (baseline ISA only: cp.async + ldmatrix + mma.sync)
// ---------------------------------------------------------------------------
__device__ __forceinline__ uint32_t smem_u32(const void* p) {
    uint32_t a;
    asm("{ .reg .u64 t; cvta.to.shared.u64 t, %1; cvt.u32.u64 %0, t; }"
        : "=r"(a) : "l"(p));
    return a;
}

#define CP_ASYNC16(sm, gp) \
    asm volatile("cp.async.cg.shared.global [%0], [%1], 16;" :: "r"((uint32_t)(sm)), "l"(gp) : "memory")
#define CP_COMMIT() asm volatile("cp.async.commit_group;" ::: "memory")
#define CP_WAIT(n)  asm volatile("cp.async.wait_group %0;" :: "n"(n) : "memory")

__device__ __forceinline__ void ldsm4(uint32_t* r, uint32_t addr) {
    asm volatile("ldmatrix.sync.aligned.m8n8.x4.shared.b16 {%0,%1,%2,%3}, [%4];"
        : "=r"(r[0]), "=r"(r[1]), "=r"(r[2]), "=r"(r[3]) : "r"(addr));
}

__device__ __forceinline__ void mma_bf16(float* c, const uint32_t* a, const uint32_t* b) {
    asm volatile(
        "mma.sync.aligned.m16n8k16.row.col.f32.bf16.bf16.f32 "
        "{%0,%1,%2,%3}, {%4,%5,%6,%7}, {%8,%9}, {%0,%1,%2,%3};"
        : "+f"(c[0]), "+f"(c[1]), "+f"(c[2]), "+f"(c[3])
        : "r"(a[0]), "r"(a[1]), "r"(a[2]), "r"(a[3]), "r"(b[0]), "r"(b[1]));
}

__device__ __forceinline__ float ex2f(float x) {
    float r; asm("ex2.approx.f32 %0, %1;" : "=f"(r) : "f"(x)); return r;
}

// pack (a -> low half, b -> high half) as bf16x2 (PTX: first src = high)
__device__ __forceinline__ uint32_t packbf2(float a, float b) {
    uint32_t r; asm("cvt.rn.bf16x2.f32 %0, %1, %2;" : "=r"(r) : "f"(b), "f"(a)); return r;
}

// swizzles: 16B-chunk XOR within a row
__device__ __forceinline__ uint32_t swz(int row, int chunk) {        // 64B rows
    return (uint32_t)(row * 64 + ((chunk ^ ((row >> 1) & 3)) << 4));
}
__device__ __forceinline__ uint32_t swz256(int row, int chunk) {     // 256B rows
    return (uint32_t)(row * 256 + ((chunk ^ (row & 7)) << 4));
}
__device__ __forceinline__ uint32_t swz128(int row, int chunk) {     // 128B rows
    return (uint32_t)(row * 128 + ((chunk ^ (row & 7)) << 4));
}

// ---------------------------------------------------------------------------
// Split fp32 -> bf16 3-term layout.
// a-side (bside=0): [hi | lo | hi] ; b-side (bside=1): [hi | hi | lo]
// ---------------------------------------------------------------------------
__global__ void split_kernel(const float* __restrict__ src,
                             __nv_bfloat16* __restrict__ dst, int bside)
{
    int idx = blockIdx.x * blockDim.x + threadIdx.x;
    int r = idx >> 10, k = idx & 1023;
    float v = src[idx];
    __nv_bfloat16 hi = __float2bfloat16(v);
    __nv_bfloat16 lo = __float2bfloat16(v - __bfloat162float(hi));
    size_t base = (size_t)r * KSPLIT;
    dst[base + k] = hi;
    dst[base + 1024 + k] = bside ? hi : lo;
    dst[base + 2048 + k] = bside ? lo : hi;
}

__global__ void bias_concat_kernel(const float* __restrict__ bq,
                                   const float* __restrict__ bk,
                                   const float* __restrict__ bv)
{
    int i = blockIdx.x * blockDim.x + threadIdx.x;   // 3072 total
    const float* s = (i < 1024) ? bq : ((i < 2048) ? bk : bv);
    g_bias_qkv[i] = s[i & 1023];
}

// ---------------------------------------------------------------------------
// HMMA bf16 GEMM (unchanged from R3): C = A2 @ B2^T + bias, K=3072
// ---------------------------------------------------------------------------
#define GK KSPLIT
#define NS (GK / 32)      // 96 stages

__global__ __launch_bounds__(256) void gemm_hmma(
    const __nv_bfloat16* __restrict__ A2, const __nv_bfloat16* __restrict__ B2,
    const float* __restrict__ bias, float* __restrict__ out0,
    float* __restrict__ outQ, float* __restrict__ outK, float* __restrict__ outV,
    int mode)
{
    __shared__ __align__(128) char sA[2][128 * 64];
    __shared__ __align__(128) char sB[2][128 * 64];

    const int tid = threadIdx.x;
    const int lane = tid & 31;
    const int wid = tid >> 5;
    const int warp_m = wid & 3;
    const int warp_n = wid >> 2;
    const int m0 = blockIdx.y * 128;
    const int n0 = blockIdx.x * 128;

    const uint32_t sbA[2] = { smem_u32(sA[0]), smem_u32(sA[1]) };
    const uint32_t sbB[2] = { smem_u32(sB[0]), smem_u32(sB[1]) };

    const __nv_bfloat16* Abase = A2 + (size_t)m0 * GK;
    const __nv_bfloat16* Bbase = B2 + (size_t)n0 * GK;

    float acc[2][8][4];
#pragma unroll
    for (int i = 0; i < 2; i++)
#pragma unroll
        for (int j = 0; j < 8; j++)
#pragma unroll
            for (int q = 0; q < 4; q++) acc[i][j][q] = 0.f;

    auto load_stage = [&](int s) {
        int b = s & 1;
        const __nv_bfloat16* Ag = Abase + s * 32;
        const __nv_bfloat16* Bg = Bbase + s * 32;
#pragma unroll
        for (int u = 0; u < 2; u++) {
            int flat = tid + u * 256;
            int r = flat >> 2, c8 = flat & 3;
            uint32_t off = swz(r, c8);
            CP_ASYNC16(sbA[b] + off, (const void*)(Ag + (size_t)r * GK + c8 * 8));
            CP_ASYNC16(sbB[b] + off, (const void*)(Bg + (size_t)r * GK + c8 * 8));
        }
        CP_COMMIT();
    };

    load_stage(0);

    for (int s = 0; s < NS; s++) {
        int b = s & 1;
        if (s + 1 < NS) { load_stage(s + 1); CP_WAIT(1); }
        else { CP_WAIT(0); }
        __syncthreads();

#pragma unroll
        for (int kk = 0; kk < 2; kk++) {
            uint32_t af[2][4];
#pragma unroll
            for (int tm = 0; tm < 2; tm++) {
                int row = warp_m * 32 + tm * 16 + (lane & 7) + ((lane >> 3) & 1) * 8;
                int chunk = kk * 2 + (lane >> 4);
                ldsm4(af[tm], sbA[b] + swz(row, chunk));
            }
            uint32_t bf[4][4];
#pragma unroll
            for (int p = 0; p < 4; p++) {
                int row = warp_n * 64 + p * 16 + (lane & 7) + (lane >> 4) * 8;
                int chunk = kk * 2 + ((lane >> 3) & 1);
                ldsm4(bf[p], sbB[b] + swz(row, chunk));
            }
#pragma unroll
            for (int tm = 0; tm < 2; tm++)
#pragma unroll
                for (int tn = 0; tn < 8; tn++) {
                    const uint32_t* bb = &bf[tn >> 1][(tn & 1) * 2];
                    mma_bf16(acc[tm][tn], af[tm], bb);
                }
        }
        __syncthreads();
    }

    const int m_base = m0 + warp_m * 32;
    const int n_base = n0 + warp_n * 64;
#pragma unroll
    for (int tm = 0; tm < 2; tm++) {
#pragma unroll
        for (int tn = 0; tn < 8; tn++) {
            int r0 = m_base + tm * 16 + (lane >> 2);
            int c0 = n_base + tn * 8 + 2 * (lane & 3);
            float bx = bias[c0], by = bias[c0 + 1];
#pragma unroll
            for (int half = 0; half < 2; half++) {
                int m = r0 + half * 8;
                float vx = acc[tm][tn][half * 2 + 0] + bx;
                float vy = acc[tm][tn][half * 2 + 1] + by;
                if (mode == 0) {
                    float2* dst = (float2*)(out0 + (size_t)m * 1024 + c0);
                    *dst = make_float2(vx, vy);
                } else {
                    int which = c0 >> 10;
                    int nn = c0 & 1023;
                    int head = nn >> 6;
                    int d0 = nn & 63;
                    int bb2 = m >> 11;
                    int t = m & (TSEQ - 1);
                    float* P = (which == 0) ? outQ : ((which == 1) ? outK : outV);
                    float2* dst = (float2*)(P +
                        (((size_t)(bb2 * NHEADS + head)) * TSEQ + t) * HDIM + d0);
                    *dst = make_float2(vx, vy);
                }
            }
        }
    }
}

// ---------------------------------------------------------------------------
// RoPE + split to bf16 hi/lo. Q gets 0.125*log2(e) folded in (exp2 domain).
// Qh/Kh layout: [bh][t][hi d0..63 | lo d0..63]
// ---------------------------------------------------------------------------
#define QSCALE (0.125f * 1.44269504088896340736f)

__global__ void rope_convert(const float* __restrict__ Q, const float* __restrict__ K,
                             __nv_bfloat16* __restrict__ Qh, __nv_bfloat16* __restrict__ Kh)
{
    int idx = blockIdx.x * blockDim.x + threadIdx.x;   // BHTOT*TSEQ*32
    int d  = idx & 31;
    int t  = (idx >> 5) & (TSEQ - 1);
    int bh = idx >> 16;

    float inv_freq = powf(10000.f, -(float)d * (1.f / 32.f));
    float s, c;
    sincosf((float)t * inv_freq, &s, &c);

    size_t base = ((size_t)bh * TSEQ + t) * HDIM;
    float q1 = Q[base + d], q2 = Q[base + d + 32];
    float k1 = K[base + d], k2 = K[base + d + 32];
    float q1r = (q1 * c - q2 * s) * QSCALE;
    float q2r = (q2 * c + q1 * s) * QSCALE;
    float k1r = k1 * c - k2 * s;
    float k2r = k2 * c + k1 * s;

    size_t ob = ((size_t)bh * TSEQ + t) * 128;
    __nv_bfloat16 h;
    h = __float2bfloat16(q1r); Qh[ob + d] = h;
    Qh[ob + 64 + d] = __float2bfloat16(q1r - __bfloat162float(h));
    h = __float2bfloat16(q2r); Qh[ob + 32 + d] = h;
    Qh[ob + 96 + d] = __float2bfloat16(q2r - __bfloat162float(h));
    h = __float2bfloat16(k1r); Kh[ob + d] = h;
    Kh[ob + 64 + d] = __float2bfloat16(k1r - __bfloat162float(h));
    h = __float2bfloat16(k2r); Kh[ob + 32 + d] = h;
    Kh[ob + 96 + d] = __float2bfloat16(k2r - __bfloat162float(h));
}

// ---------------------------------------------------------------------------
// V transpose + split: g_V [bh][t][64] fp32 -> Vt [bh][d' (hi0-63|lo64-127)][t]
// ---------------------------------------------------------------------------
__global__ void v_convert(const float* __restrict__ V, __nv_bfloat16* __restrict__ Vt)
{
    __shared__ float tile[64][65];
    int bh = blockIdx.y;
    int t0 = blockIdx.x * 64;
    int tid = threadIdx.x;   // 256
#pragma unroll
    for (int i = 0; i < 16; i++) {
        int flat = tid + i * 256;
        int r = flat >> 6, d = flat & 63;
        tile[r][d] = V[((size_t)bh * TSEQ + t0 + r) * HDIM + d];
    }
    __syncthreads();
#pragma unroll
    for (int i = 0; i < 16; i++) {
        int flat = tid + i * 256;
        int d = flat >> 6, c = flat & 63;
        float v = tile[c][d];
        __nv_bfloat16 h = __float2bfloat16(v);
        Vt[((size_t)bh * 128 + d) * TSEQ + t0 + c] = h;
        Vt[((size_t)bh * 128 + 64 + d) * TSEQ + t0 + c] =
            __float2bfloat16(v - __bfloat162float(h));
    }
}

// ---------------------------------------------------------------------------
// HMMA flash attention. CTA: 128 q-rows x one (b,h); 4 warps x 32 rows.
// Key tiles of 64. QK and PV both 3-term split-bf16. exp2-domain softmax
// (scale+log2e folded into Q). Epilogue writes split ctx into g_A2 directly.
// smem: Qs 32KB + 2x Ks 16KB + 2x Vs 16KB = 96KB.
// ---------------------------------------------------------------------------
#define AQ 128
#define AK 64
#define NKT (TSEQ / AK)   // 32
#define ATTN_SMEM 98304

__global__ __launch_bounds__(128) void attn_mma(
    const __nv_bfloat16* __restrict__ Qh, const __nv_bfloat16* __restrict__ Kh,
    const __nv_bfloat16* __restrict__ Vt, __nv_bfloat16* __restrict__ A2)
{
    extern __shared__ __align__(128) char smem[];
    const uint32_t sQ = smem_u32(smem);
    const uint32_t sK[2] = { sQ + 32768, sQ + 32768 + 16384 };
    const uint32_t sV[2] = { sQ + 65536, sQ + 65536 + 16384 };

    const int tid = threadIdx.x, lane = tid & 31, wid = tid >> 5;
    const int qtile = blockIdx.x, bh = blockIdx.y;

    const __nv_bfloat16* Qg = Qh + ((size_t)bh * TSEQ + qtile * AQ) * 128;
    const __nv_bfloat16* Kg = Kh + (size_t)bh * TSEQ * 128;
    const __nv_bfloat16* Vg = Vt + (size_t)bh * 128 * TSEQ;

    auto loadKV = [&](int t) {
        int b = t & 1;
        const __nv_bfloat16* Kt = Kg + (size_t)t * AK * 128;
#pragma unroll
        for (int u = 0; u < 8; u++) {
            int flat = tid + u * 128;          // 0..1023
            int r = flat >> 4, c = flat & 15;
            CP_ASYNC16(sK[b] + swz256(r, c), (const void*)(Kt + r * 128 + c * 8));
        }
        const __nv_bfloat16* Vtt = Vg + t * AK;
#pragma unroll
        for (int u = 0; u < 8; u++) {
            int flat = tid + u * 128;
            int r = flat >> 3, c = flat & 7;
            CP_ASYNC16(sV[b] + swz128(r, c), (const void*)(Vtt + (size_t)r * TSEQ + c * 8));
        }
    };

    // prologue: Q tile + KV tile 0 in one group
#pragma unroll
    for (int u = 0; u < 16; u++) {
        int flat = tid + u * 128;              // 0..2047
        int r = flat >> 4, c = flat & 15;
        CP_ASYNC16(sQ + swz256(r, c), (const void*)(Qg + r * 128 + c * 8));
    }
    loadKV(0);
    CP_COMMIT();

    float O[2][8][4];
#pragma unroll
    for (int i = 0; i < 2; i++)
#pragma unroll
        for (int j = 0; j < 8; j++)
#pragma unroll
            for (int q = 0; q < 4; q++) O[i][j][q] = 0.f;
    float mrow[2][2] = { {-1e30f, -1e30f}, {-1e30f, -1e30f} };
    float lrow[2][2] = { {0.f, 0.f}, {0.f, 0.f} };

    for (int t = 0; t < NKT; t++) {
        int b = t & 1;
        if (t + 1 < NKT) { loadKV(t + 1); CP_COMMIT(); CP_WAIT(1); }
        else { CP_WAIT(0); }
        __syncthreads();

        // ---- QK: S[32 rows][64 keys], 3 split terms ----
        float S[2][8][4];
#pragma unroll
        for (int i = 0; i < 2; i++)
#pragma unroll
            for (int j = 0; j < 8; j++)
#pragma unroll
                for (int q = 0; q < 4; q++) S[i][j][q] = 0.f;

#pragma unroll
        for (int term = 0; term < 3; term++) {
            const int ach = (term == 1) ? 8 : 0;
            const int bch = (term == 2) ? 8 : 0;
#pragma unroll
            for (int kk = 0; kk < 4; kk++) {
                uint32_t af[2][4];
#pragma unroll
                for (int tm = 0; tm < 2; tm++) {
                    int row = wid * 32 + tm * 16 + (lane & 7) + ((lane >> 3) & 1) * 8;
                    int chunk = ach + kk * 2 + (lane >> 4);
                    ldsm4(af[tm], sQ + swz256(row, chunk));
                }
                uint32_t bf4[4][4];
#pragma unroll
                for (int p = 0; p < 4; p++) {
                    int row = p * 16 + (lane & 7) + (lane >> 4) * 8;
                    int chunk = bch + kk * 2 + ((lane >> 3) & 1);
                    ldsm4(bf4[p], sK[b] + swz256(row, chunk));
                }
#pragma unroll
                for (int tm = 0; tm < 2; tm++)
#pragma unroll
                    for (int tn = 0; tn < 8; tn++)
                        mma_bf16(S[tm][tn], af[tm], &bf4[tn >> 1][(tn & 1) * 2]);
            }
        }

        // ---- online softmax (exp2 domain) + P pack ----
        uint32_t Ppk[2][2][16];   // [tm][hi/lo][2*tn + rowhalf]
#pragma unroll
        for (int tm = 0; tm < 2; tm++) {
#pragma unroll
            for (int rh = 0; rh < 2; rh++) {
                float mx = S[tm][0][rh * 2];
#pragma unroll
                for (int tn = 0; tn < 8; tn++) {
                    mx = fmaxf(mx, S[tm][tn][rh * 2 + 0]);
                    mx = fmaxf(mx, S[tm][tn][rh * 2 + 1]);
                }
                mx = fmaxf(mx, __shfl_xor_sync(0xffffffffu, mx, 1));
                mx = fmaxf(mx, __shfl_xor_sync(0xffffffffu, mx, 2));
                float mold = mrow[tm][rh];
                float mnew = fmaxf(mold, mx);
                float corr = ex2f(mold - mnew);
                mrow[tm][rh] = mnew;
                float rsum = 0.f;
#pragma unroll
                for (int tn = 0; tn < 8; tn++) {
                    float p0 = ex2f(S[tm][tn][rh * 2 + 0] - mnew);
                    float p1 = ex2f(S[tm][tn][rh * 2 + 1] - mnew);
                    rsum += p0 + p1;
                    float h0 = __bfloat162float(__float2bfloat16(p0));
                    float h1 = __bfloat162float(__float2bfloat16(p1));
                    Ppk[tm][0][tn * 2 + rh] = packbf2(p0, p1);
                    Ppk[tm][1][tn * 2 + rh] = packbf2(p0 - h0, p1 - h1);
                    O[tm][tn][rh * 2 + 0] *= corr;
                    O[tm][tn][rh * 2 + 1] *= corr;
                }
                rsum += __shfl_xor_sync(0xffffffffu, rsum, 1);
                rsum += __shfl_xor_sync(0xffffffffu, rsum, 2);
                lrow[tm][rh] = lrow[tm][rh] * corr + rsum;
            }
        }

        // ---- PV: O += P @ V, 3 split terms ----
#pragma unroll
        for (int term = 0; term < 3; term++) {
            const int hsel = (term == 1) ? 1 : 0;
            const int vbase = (term == 2) ? 64 : 0;
#pragma unroll
            for (int kk = 0; kk < 4; kk++) {
                uint32_t bfv[4][4];
#pragma unroll
                for (int p = 0; p < 4; p++) {
                    int row = vbase + p * 16 + (lane & 7) + (lane >> 4) * 8;
                    int chunk = kk * 2 + ((lane >> 3) & 1);
                    ldsm4(bfv[p], sV[b] + swz128(row, chunk));
                }
#pragma unroll
                for (int tm = 0; tm < 2; tm++)
#pragma unroll
                    for (int tn = 0; tn < 8; tn++)
                        mma_bf16(O[tm][tn], &Ppk[tm][hsel][4 * kk],
                                 &bfv[tn >> 1][(tn & 1) * 2]);
            }
        }
        __syncthreads();
    }

    // ---- epilogue: write split ctx [hi|lo|hi] into A2 ----
    const int bb = bh >> 4, h = bh & 15;
#pragma unroll
    for (int tm = 0; tm < 2; tm++) {
#pragma unroll
        for (int rh = 0; rh < 2; rh++) {
            float inv = 1.f / lrow[tm][rh];
            int trow = qtile * AQ + wid * 32 + tm * 16 + rh * 8 + (lane >> 2);
            size_t m = (size_t)bb * TSEQ + trow;
            __nv_bfloat16* rowp = A2 + m * KSPLIT + h * 64;
#pragma unroll
            for (int tn = 0; tn < 8; tn++) {
                float o0 = O[tm][tn][rh * 2 + 0] * inv;
                float o1 = O[tm][tn][rh * 2 + 1] * inv;
                int d = tn * 8 + (lane & 3) * 2;
                uint32_t hi2 = packbf2(o0, o1);
                float h0 = __bfloat162float(__float2bfloat16(o0));
                float h1 = __bfloat162float(__float2bfloat16(o1));
                uint32_t lo2 = packbf2(o0 - h0, o1 - h1);
                *(uint32_t*)(rowp + d) = hi2;
                *(uint32_t*)(rowp + 1024 + d) = lo2;
                *(uint32_t*)(rowp + 2048 + d) = hi2;
            }
        }
    }
}

// ---------------------------------------------------------------------------
// Launch
// ---------------------------------------------------------------------------
extern "C" void kernel_launch(void* const* d_in, const int* in_sizes, int n_in,
                              void* d_out, int out_size)
{
    const float* x  = (const float*)d_in[0];
    const float* Wq = (const float*)d_in[1];
    const float* bq = (const float*)d_in[2];
    const float* Wk = (const float*)d_in[3];
    const float* bk = (const float*)d_in[4];
    const float* Wv = (const float*)d_in[5];
    const float* bv = (const float*)d_in[6];
    const float* Wo = (const float*)d_in[7];
    const float* bo = (const float*)d_in[8];
    float* out = (float*)d_out;

    float *Qp, *Kp, *Vp, *BIp;
    __nv_bfloat16 *A2p, *Bqkvp, *Bop, *Qhp, *Khp, *Vtp;
    cudaGetSymbolAddress((void**)&Qp, g_Q);
    cudaGetSymbolAddress((void**)&Kp, g_K);
    cudaGetSymbolAddress((void**)&Vp, g_V);
    cudaGetSymbolAddress((void**)&A2p, g_A2);
    cudaGetSymbolAddress((void**)&Bqkvp, g_Bqkv);
    cudaGetSymbolAddress((void**)&Bop, g_Bo);
    cudaGetSymbolAddress((void**)&BIp, g_bias_qkv);
    cudaGetSymbolAddress((void**)&Qhp, g_Qh);
    cudaGetSymbolAddress((void**)&Khp, g_Kh);
    cudaGetSymbolAddress((void**)&Vtp, g_Vt);

    cudaFuncSetAttribute(attn_mma, cudaFuncAttributeMaxDynamicSharedMemorySize, ATTN_SMEM);

    // split conversions
    split_kernel<<<(MROWS * 1024) / 256, 256>>>(x, A2p, 0);
    split_kernel<<<(1024 * 1024) / 256, 256>>>(Wq, Bqkvp + (size_t)0 * 1024 * KSPLIT, 1);
    split_kernel<<<(1024 * 1024) / 256, 256>>>(Wk, Bqkvp + (size_t)1 * 1024 * KSPLIT, 1);
    split_kernel<<<(1024 * 1024) / 256, 256>>>(Wv, Bqkvp + (size_t)2 * 1024 * KSPLIT, 1);
    split_kernel<<<(1024 * 1024) / 256, 256>>>(Wo, Bop, 1);
    bias_concat_kernel<<<12, 256>>>(bq, bk, bv);

    // fused QKV projection -> fp32 [B,H,T,Dh]
    gemm_hmma<<<dim3(3072 / 128, MROWS / 128), 256>>>(
        A2p, Bqkvp, BIp, nullptr, Qp, Kp, Vp, 1);

    // RoPE + bf16 split conversions
    rope_convert<<<(BHTOT * TSEQ * 32) / 256, 256>>>(Qp, Kp, Qhp, Khp);
    v_convert<<<dim3(TSEQ / 64, BHTOT), 256>>>(Vp, Vtp);

    // HMMA flash attention -> split ctx in g_A2
    attn_mma<<<dim3(TSEQ / AQ, BHTOT), 128, ATTN_SMEM>>>(Qhp, Khp, Vtp, A2p);

    // output projection -> d_out
    gemm_hmma<<<dim3(1024 / 128, MROWS / 128), 256>>>(
        A2p, Bop, bo, out, nullptr, nullptr, nullptr, 0);

    (void)in_sizes; (void)n_in; (void)out_size;
}

// round 7
// speedup vs baseline: 3.7378x; 1.1967x over previous
#include <cuda_runtime.h>
#include <cuda_bf16.h>
#include <math.h>
#include <stdint.h>

// Problem constants
#define BATCH  2
#define TSEQ   2048
#define DMODEL 1024
#define NHEADS 16
#define HDIM   64
#define BHTOT  (BATCH * NHEADS)     // 32
#define MROWS  (BATCH * TSEQ)       // 4096
#define KSPLIT 3072                 // split-bf16 3-term K

// ---------------------------------------------------------------------------
// Scratch
// ---------------------------------------------------------------------------
__device__ float g_Q[BHTOT * TSEQ * HDIM];     // [B,H,T,Dh] fp32 (pre-rope)
__device__ float g_K[BHTOT * TSEQ * HDIM];
__device__ float g_V[BHTOT * TSEQ * HDIM];
__device__ __nv_bfloat16 g_Qh[(size_t)BHTOT * TSEQ * 128];  // [bh][t][hi64|lo64]
__device__ __nv_bfloat16 g_Kh[(size_t)BHTOT * TSEQ * 128];
__device__ __nv_bfloat16 g_Vt[(size_t)BHTOT * 128 * TSEQ];  // [bh][d'128][t]
__device__ __nv_bfloat16 g_A2[(size_t)MROWS * KSPLIT];    // split activations
__device__ __nv_bfloat16 g_Bqkv[(size_t)3072 * KSPLIT];   // split Wq|Wk|Wv
__device__ __nv_bfloat16 g_Bo[(size_t)1024 * KSPLIT];     // split Wo
__device__ float g_bias_qkv[3072];

// ---------------------------------------------------------------------------
// Helpers
// ---------------------------------------------------------------------------
__device__ __forceinline__ uint32_t smem_u32(const void* p) {
    uint32_t a;
    asm("{ .reg .u64 t; cvta.to.shared.u64 t, %1; cvt.u32.u64 %0, t; }"
        : "=r"(a) : "l"(p));
    return a;
}

#define CP_ASYNC16(sm, gp) \
    asm volatile("cp.async.cg.shared.global [%0], [%1], 16;" :: "r"((uint32_t)(sm)), "l"(gp) : "memory")
#define CP_COMMIT() asm volatile("cp.async.commit_group;" ::: "memory")
#define CP_WAIT(n)  asm volatile("cp.async.wait_group %0;" :: "n"(n) : "memory")

__device__ __forceinline__ void ldsm4(uint32_t* r, uint32_t addr) {
    asm volatile("ldmatrix.sync.aligned.m8n8.x4.shared.b16 {%0,%1,%2,%3}, [%4];"
        : "=r"(r[0]), "=r"(r[1]), "=r"(r[2]), "=r"(r[3]) : "r"(addr));
}

__device__ __forceinline__ void mma_bf16(float* c, const uint32_t* a, const uint32_t* b) {
    asm volatile(
        "mma.sync.aligned.m16n8k16.row.col.f32.bf16.bf16.f32 "
        "{%0,%1,%2,%3}, {%4,%5,%6,%7}, {%8,%9}, {%0,%1,%2,%3};"
        : "+f"(c[0]), "+f"(c[1]), "+f"(c[2]), "+f"(c[3])
        : "r"(a[0]), "r"(a[1]), "r"(a[2]), "r"(a[3]), "r"(b[0]), "r"(b[1]));
}

__device__ __forceinline__ float ex2f(float x) {
    float r; asm("ex2.approx.f32 %0, %1;" : "=f"(r) : "f"(x)); return r;
}

__device__ __forceinline__ uint32_t packbf2(float a, float b) {
    uint32_t r; asm("cvt.rn.bf16x2.f32 %0, %1, %2;" : "=r"(r) : "f"(b), "f"(a)); return r;
}

// swizzles: 16B-chunk XOR within a row
__device__ __forceinline__ uint32_t swz256(int row, int chunk) {     // 256B rows
    return (uint32_t)(row * 256 + ((chunk ^ (row & 7)) << 4));
}
__device__ __forceinline__ uint32_t swz128(int row, int chunk) {     // 128B rows
    return (uint32_t)(row * 128 + ((chunk ^ (row & 7)) << 4));
}

// ---------------------------------------------------------------------------
// Split fp32 -> bf16 3-term layout.
// a-side (bside=0): [hi | lo | hi] ; b-side (bside=1): [hi | hi | lo]
// ---------------------------------------------------------------------------
__global__ void split_kernel(const float* __restrict__ src,
                             __nv_bfloat16* __restrict__ dst, int bside)
{
    int idx = blockIdx.x * blockDim.x + threadIdx.x;
    int r = idx >> 10, k = idx & 1023;
    float v = src[idx];
    __nv_bfloat16 hi = __float2bfloat16(v);
    __nv_bfloat16 lo = __float2bfloat16(v - __bfloat162float(hi));
    size_t base = (size_t)r * KSPLIT;
    dst[base + k] = hi;
    dst[base + 1024 + k] = bside ? hi : lo;
    dst[base + 2048 + k] = bside ? lo : hi;
}

__global__ void bias_concat_kernel(const float* __restrict__ bq,
                                   const float* __restrict__ bk,
                                   const float* __restrict__ bv)
{
    int i = blockIdx.x * blockDim.x + threadIdx.x;   // 3072 total
    const float* s = (i < 1024) ? bq : ((i < 2048) ? bk : bv);
    g_bias_qkv[i] = s[i & 1023];
}

// ---------------------------------------------------------------------------
// HMMA bf16 GEMM: C = A2 @ B2^T + bias, K=3072.
// CTA 128x128, 8 warps (4m x 2n), BK=64, 3-stage cp.async pipeline,
// ONE __syncthreads per stage. smem 96KB dynamic, 2 CTAs/SM.
// ---------------------------------------------------------------------------
#define GK KSPLIT
#define GBK 64
#define GNS (GK / GBK)      // 48 stages
#define GSTG 3
#define GEMM_SMEM (GSTG * 2 * 128 * 128)   // 98304

__global__ __launch_bounds__(256, 2) void gemm_hmma(
    const __nv_bfloat16* __restrict__ A2, const __nv_bfloat16* __restrict__ B2,
    const float* __restrict__ bias, float* __restrict__ out0,
    float* __restrict__ outQ, float* __restrict__ outK, float* __restrict__ outV,
    int mode)
{
    extern __shared__ __align__(128) char gsm[];
    const uint32_t base = smem_u32(gsm);

    const int tid = threadIdx.x;
    const int lane = tid & 31;
    const int wid = tid >> 5;
    const int warp_m = wid & 3;
    const int warp_n = wid >> 2;
    const int m0 = blockIdx.y * 128;
    const int n0 = blockIdx.x * 128;

    // per-stage buffers: A at +0, B at +16384 within each 32KB stage
    uint32_t sbA[GSTG], sbB[GSTG];
#pragma unroll
    for (int i = 0; i < GSTG; i++) {
        sbA[i] = base + i * 32768;
        sbB[i] = base + i * 32768 + 16384;
    }

    const __nv_bfloat16* Abase = A2 + (size_t)m0 * GK;
    const __nv_bfloat16* Bbase = B2 + (size_t)n0 * GK;

    float acc[2][8][4];
#pragma unroll
    for (int i = 0; i < 2; i++)
#pragma unroll
        for (int j = 0; j < 8; j++)
#pragma unroll
            for (int q = 0; q < 4; q++) acc[i][j][q] = 0.f;

    // stage loader: 128 rows x 8 chunks (16B) for A and B  (BK=64 -> 128B rows)
    auto load_stage = [&](int s) {
        int b = s % GSTG;
        const __nv_bfloat16* Ag = Abase + s * GBK;
        const __nv_bfloat16* Bg = Bbase + s * GBK;
#pragma unroll
        for (int u = 0; u < 4; u++) {
            int flat = tid + u * 256;            // 0..1023
            int r = flat >> 3, c = flat & 7;
            uint32_t off = swz128(r, c);
            CP_ASYNC16(sbA[b] + off, (const void*)(Ag + (size_t)r * GK + c * 8));
            CP_ASYNC16(sbB[b] + off, (const void*)(Bg + (size_t)r * GK + c * 8));
        }
        CP_COMMIT();
    };

    load_stage(0);
    load_stage(1);

    for (int s = 0; s < GNS; s++) {
        int b = s % GSTG;
        if (s < GNS - 1) { CP_WAIT(1); } else { CP_WAIT(0); }
        __syncthreads();

#pragma unroll
        for (int kk = 0; kk < 4; kk++) {
            uint32_t af[2][4];
#pragma unroll
            for (int tm = 0; tm < 2; tm++) {
                int row = warp_m * 32 + tm * 16 + (lane & 7) + ((lane >> 3) & 1) * 8;
                int chunk = kk * 2 + (lane >> 4);
                ldsm4(af[tm], sbA[b] + swz128(row, chunk));
            }
            uint32_t bf[4][4];
#pragma unroll
            for (int p = 0; p < 4; p++) {
                int row = warp_n * 64 + p * 16 + (lane & 7) + (lane >> 4) * 8;
                int chunk = kk * 2 + ((lane >> 3) & 1);
                ldsm4(bf[p], sbB[b] + swz128(row, chunk));
            }
#pragma unroll
            for (int tm = 0; tm < 2; tm++)
#pragma unroll
                for (int tn = 0; tn < 8; tn++)
                    mma_bf16(acc[tm][tn], af[tm], &bf[tn >> 1][(tn & 1) * 2]);
        }

        if (s + 2 < GNS) load_stage(s + 2);
    }

    const int m_base = m0 + warp_m * 32;
    const int n_base = n0 + warp_n * 64;
#pragma unroll
    for (int tm = 0; tm < 2; tm++) {
#pragma unroll
        for (int tn = 0; tn < 8; tn++) {
            int r0 = m_base + tm * 16 + (lane >> 2);
            int c0 = n_base + tn * 8 + 2 * (lane & 3);
            float bx = bias[c0], by = bias[c0 + 1];
#pragma unroll
            for (int half = 0; half < 2; half++) {
                int m = r0 + half * 8;
                float vx = acc[tm][tn][half * 2 + 0] + bx;
                float vy = acc[tm][tn][half * 2 + 1] + by;
                if (mode == 0) {
                    float2* dst = (float2*)(out0 + (size_t)m * 1024 + c0);
                    *dst = make_float2(vx, vy);
                } else {
                    int which = c0 >> 10;
                    int nn = c0 & 1023;
                    int head = nn >> 6;
                    int d0 = nn & 63;
                    int bb2 = m >> 11;
                    int t = m & (TSEQ - 1);
                    float* P = (which == 0) ? outQ : ((which == 1) ? outK : outV);
                    float2* dst = (float2*)(P +
                        (((size_t)(bb2 * NHEADS + head)) * TSEQ + t) * HDIM + d0);
                    *dst = make_float2(vx, vy);
                }
            }
        }
    }
}

// ---------------------------------------------------------------------------
// RoPE + split to bf16 hi/lo. Q gets 0.125*log2(e) folded in (exp2 domain).
// ---------------------------------------------------------------------------
#define QSCALE (0.125f * 1.44269504088896340736f)

__global__ void rope_convert(const float* __restrict__ Q, const float* __restrict__ K,
                             __nv_bfloat16* __restrict__ Qh, __nv_bfloat16* __restrict__ Kh)
{
    int idx = blockIdx.x * blockDim.x + threadIdx.x;   // BHTOT*TSEQ*32
    int d  = idx & 31;
    int t  = (idx >> 5) & (TSEQ - 1);
    int bh = idx >> 16;

    float inv_freq = powf(10000.f, -(float)d * (1.f / 32.f));
    float s, c;
    sincosf((float)t * inv_freq, &s, &c);

    size_t base = ((size_t)bh * TSEQ + t) * HDIM;
    float q1 = Q[base + d], q2 = Q[base + d + 32];
    float k1 = K[base + d], k2 = K[base + d + 32];
    float q1r = (q1 * c - q2 * s) * QSCALE;
    float q2r = (q2 * c + q1 * s) * QSCALE;
    float k1r = k1 * c - k2 * s;
    float k2r = k2 * c + k1 * s;

    size_t ob = ((size_t)bh * TSEQ + t) * 128;
    __nv_bfloat16 h;
    h = __float2bfloat16(q1r); Qh[ob + d] = h;
    Qh[ob + 64 + d] = __float2bfloat16(q1r - __bfloat162float(h));
    h = __float2bfloat16(q2r); Qh[ob + 32 + d] = h;
    Qh[ob + 96 + d] = __float2bfloat16(q2r - __bfloat162float(h));
    h = __float2bfloat16(k1r); Kh[ob + d] = h;
    Kh[ob + 64 + d] = __float2bfloat16(k1r - __bfloat162float(h));
    h = __float2bfloat16(k2r); Kh[ob + 32 + d] = h;
    Kh[ob + 96 + d] = __float2bfloat16(k2r - __bfloat162float(h));
}

// ---------------------------------------------------------------------------
// V transpose + split
// ---------------------------------------------------------------------------
__global__ void v_convert(const float* __restrict__ V, __nv_bfloat16* __restrict__ Vt)
{
    __shared__ float tile[64][65];
    int bh = blockIdx.y;
    int t0 = blockIdx.x * 64;
    int tid = threadIdx.x;   // 256
#pragma unroll
    for (int i = 0; i < 16; i++) {
        int flat = tid + i * 256;
        int r = flat >> 6, d = flat & 63;
        tile[r][d] = V[((size_t)bh * TSEQ + t0 + r) * HDIM + d];
    }
    __syncthreads();
#pragma unroll
    for (int i = 0; i < 16; i++) {
        int flat = tid + i * 256;
        int d = flat >> 6, c = flat & 63;
        float v = tile[c][d];
        __nv_bfloat16 h = __float2bfloat16(v);
        Vt[((size_t)bh * 128 + d) * TSEQ + t0 + c] = h;
        Vt[((size_t)bh * 128 + 64 + d) * TSEQ + t0 + c] =
            __float2bfloat16(v - __bfloat162float(h));
    }
}

// ---------------------------------------------------------------------------
// HMMA flash attention (unchanged from R4)
// ---------------------------------------------------------------------------
#define AQ 128
#define AK 64
#define NKT (TSEQ / AK)   // 32
#define ATTN_SMEM 98304

__global__ __launch_bounds__(128) void attn_mma(
    const __nv_bfloat16* __restrict__ Qh, const __nv_bfloat16* __restrict__ Kh,
    const __nv_bfloat16* __restrict__ Vt, __nv_bfloat16* __restrict__ A2)
{
    extern __shared__ __align__(128) char smem[];
    const uint32_t sQ = smem_u32(smem);
    const uint32_t sK[2] = { sQ + 32768, sQ + 32768 + 16384 };
    const uint32_t sV[2] = { sQ + 65536, sQ + 65536 + 16384 };

    const int tid = threadIdx.x, lane = tid & 31, wid = tid >> 5;
    const int qtile = blockIdx.x, bh = blockIdx.y;

    const __nv_bfloat16* Qg = Qh + ((size_t)bh * TSEQ + qtile * AQ) * 128;
    const __nv_bfloat16* Kg = Kh + (size_t)bh * TSEQ * 128;
    const __nv_bfloat16* Vg = Vt + (size_t)bh * 128 * TSEQ;

    auto loadKV = [&](int t) {
        int b = t & 1;
        const __nv_bfloat16* Kt = Kg + (size_t)t * AK * 128;
#pragma unroll
        for (int u = 0; u < 8; u++) {
            int flat = tid + u * 128;
            int r = flat >> 4, c = flat & 15;
            CP_ASYNC16(sK[b] + swz256(r, c), (const void*)(Kt + r * 128 + c * 8));
        }
        const __nv_bfloat16* Vtt = Vg + t * AK;
#pragma unroll
        for (int u = 0; u < 8; u++) {
            int flat = tid + u * 128;
            int r = flat >> 3, c = flat & 7;
            CP_ASYNC16(sV[b] + swz128(r, c), (const void*)(Vtt + (size_t)r * TSEQ + c * 8));
        }
    };

#pragma unroll
    for (int u = 0; u < 16; u++) {
        int flat = tid + u * 128;
        int r = flat >> 4, c = flat & 15;
        CP_ASYNC16(sQ + swz256(r, c), (const void*)(Qg + r * 128 + c * 8));
    }
    loadKV(0);
    CP_COMMIT();

    float O[2][8][4];
#pragma unroll
    for (int i = 0; i < 2; i++)
#pragma unroll
        for (int j = 0; j < 8; j++)
#pragma unroll
            for (int q = 0; q < 4; q++) O[i][j][q] = 0.f;
    float mrow[2][2] = { {-1e30f, -1e30f}, {-1e30f, -1e30f} };
    float lrow[2][2] = { {0.f, 0.f}, {0.f, 0.f} };

    for (int t = 0; t < NKT; t++) {
        int b = t & 1;
        if (t + 1 < NKT) { loadKV(t + 1); CP_COMMIT(); CP_WAIT(1); }
        else { CP_WAIT(0); }
        __syncthreads();

        float S[2][8][4];
#pragma unroll
        for (int i = 0; i < 2; i++)
#pragma unroll
            for (int j = 0; j < 8; j++)
#pragma unroll
                for (int q = 0; q < 4; q++) S[i][j][q] = 0.f;

#pragma unroll
        for (int term = 0; term < 3; term++) {
            const int ach = (term == 1) ? 8 : 0;
            const int bch = (term == 2) ? 8 : 0;
#pragma unroll
            for (int kk = 0; kk < 4; kk++) {
                uint32_t af[2][4];
#pragma unroll
                for (int tm = 0; tm < 2; tm++) {
                    int row = wid * 32 + tm * 16 + (lane & 7) + ((lane >> 3) & 1) * 8;
                    int chunk = ach + kk * 2 + (lane >> 4);
                    ldsm4(af[tm], sQ + swz256(row, chunk));
                }
                uint32_t bf4[4][4];
#pragma unroll
                for (int p = 0; p < 4; p++) {
                    int row = p * 16 + (lane & 7) + (lane >> 4) * 8;
                    int chunk = bch + kk * 2 + ((lane >> 3) & 1);
                    ldsm4(bf4[p], sK[b] + swz256(row, chunk));
                }
#pragma unroll
                for (int tm = 0; tm < 2; tm++)
#pragma unroll
                    for (int tn = 0; tn < 8; tn++)
                        mma_bf16(S[tm][tn], af[tm], &bf4[tn >> 1][(tn & 1) * 2]);
            }
        }

        uint32_t Ppk[2][2][16];
#pragma unroll
        for (int tm = 0; tm < 2; tm++) {
#pragma unroll
            for (int rh = 0; rh < 2; rh++) {
                float mx = S[tm][0][rh * 2];
#pragma unroll
                for (int tn = 0; tn < 8; tn++) {
                    mx = fmaxf(mx, S[tm][tn][rh * 2 + 0]);
                    mx = fmaxf(mx, S[tm][tn][rh * 2 + 1]);
                }
                mx = fmaxf(mx, __shfl_xor_sync(0xffffffffu, mx, 1));
                mx = fmaxf(mx, __shfl_xor_sync(0xffffffffu, mx, 2));
                float mold = mrow[tm][rh];
                float mnew = fmaxf(mold, mx);
                float corr = ex2f(mold - mnew);
                mrow[tm][rh] = mnew;
                float rsum = 0.f;
#pragma unroll
                for (int tn = 0; tn < 8; tn++) {
                    float p0 = ex2f(S[tm][tn][rh * 2 + 0] - mnew);
                    float p1 = ex2f(S[tm][tn][rh * 2 + 1] - mnew);
                    rsum += p0 + p1;
                    float h0 = __bfloat162float(__float2bfloat16(p0));
                    float h1 = __bfloat162float(__float2bfloat16(p1));
                    Ppk[tm][0][tn * 2 + rh] = packbf2(p0, p1);
                    Ppk[tm][1][tn * 2 + rh] = packbf2(p0 - h0, p1 - h1);
                    O[tm][tn][rh * 2 + 0] *= corr;
                    O[tm][tn][rh * 2 + 1] *= corr;
                }
                rsum += __shfl_xor_sync(0xffffffffu, rsum, 1);
                rsum += __shfl_xor_sync(0xffffffffu, rsum, 2);
                lrow[tm][rh] = lrow[tm][rh] * corr + rsum;
            }
        }

#pragma unroll
        for (int term = 0; term < 3; term++) {
            const int hsel = (term == 1) ? 1 : 0;
            const int vbase = (term == 2) ? 64 : 0;
#pragma unroll
            for (int kk = 0; kk < 4; kk++) {
                uint32_t bfv[4][4];
#pragma unroll
                for (int p = 0; p < 4; p++) {
                    int row = vbase + p * 16 + (lane & 7) + (lane >> 4) * 8;
                    int chunk = kk * 2 + ((lane >> 3) & 1);
                    ldsm4(bfv[p], sV[b] + swz128(row, chunk));
                }
#pragma unroll
                for (int tm = 0; tm < 2; tm++)
#pragma unroll
                    for (int tn = 0; tn < 8; tn++)
                        mma_bf16(O[tm][tn], &Ppk[tm][hsel][4 * kk],
                                 &bfv[tn >> 1][(tn & 1) * 2]);
            }
        }
        __syncthreads();
    }

    const int bb = bh >> 4, h = bh & 15;
#pragma unroll
    for (int tm = 0; tm < 2; tm++) {
#pragma unroll
        for (int rh = 0; rh < 2; rh++) {
            float inv = 1.f / lrow[tm][rh];
            int trow = qtile * AQ + wid * 32 + tm * 16 + rh * 8 + (lane >> 2);
            size_t m = (size_t)bb * TSEQ + trow;
            __nv_bfloat16* rowp = A2 + m * KSPLIT + h * 64;
#pragma unroll
            for (int tn = 0; tn < 8; tn++) {
                float o0 = O[tm][tn][rh * 2 + 0] * inv;
                float o1 = O[tm][tn][rh * 2 + 1] * inv;
                int d = tn * 8 + (lane & 3) * 2;
                uint32_t hi2 = packbf2(o0, o1);
                float h0 = __bfloat162float(__float2bfloat16(o0));
                float h1 = __bfloat162float(__float2bfloat16(o1));
                uint32_t lo2 = packbf2(o0 - h0, o1 - h1);
                *(uint32_t*)(rowp + d) = hi2;
                *(uint32_t*)(rowp + 1024 + d) = lo2;
                *(uint32_t*)(rowp + 2048 + d) = hi2;
            }
        }
    }
}

// ---------------------------------------------------------------------------
// Launch
// ---------------------------------------------------------------------------
extern "C" void kernel_launch(void* const* d_in, const int* in_sizes, int n_in,
                              void* d_out, int out_size)
{
    const float* x  = (const float*)d_in[0];
    const float* Wq = (const float*)d_in[1];
    const float* bq = (const float*)d_in[2];
    const float* Wk = (const float*)d_in[3];
    const float* bk = (const float*)d_in[4];
    const float* Wv = (const float*)d_in[5];
    const float* bv = (const float*)d_in[6];
    const float* Wo = (const float*)d_in[7];
    const float* bo = (const float*)d_in[8];
    float* out = (float*)d_out;

    float *Qp, *Kp, *Vp, *BIp;
    __nv_bfloat16 *A2p, *Bqkvp, *Bop, *Qhp, *Khp, *Vtp;
    cudaGetSymbolAddress((void**)&Qp, g_Q);
    cudaGetSymbolAddress((void**)&Kp, g_K);
    cudaGetSymbolAddress((void**)&Vp, g_V);
    cudaGetSymbolAddress((void**)&A2p, g_A2);
    cudaGetSymbolAddress((void**)&Bqkvp, g_Bqkv);
    cudaGetSymbolAddress((void**)&Bop, g_Bo);
    cudaGetSymbolAddress((void**)&BIp, g_bias_qkv);
    cudaGetSymbolAddress((void**)&Qhp, g_Qh);
    cudaGetSymbolAddress((void**)&Khp, g_Kh);
    cudaGetSymbolAddress((void**)&Vtp, g_Vt);

    cudaFuncSetAttribute(attn_mma, cudaFuncAttributeMaxDynamicSharedMemorySize, ATTN_SMEM);
    cudaFuncSetAttribute(gemm_hmma, cudaFuncAttributeMaxDynamicSharedMemorySize, GEMM_SMEM);

    // split conversions
    split_kernel<<<(MROWS * 1024) / 256, 256>>>(x, A2p, 0);
    split_kernel<<<(1024 * 1024) / 256, 256>>>(Wq, Bqkvp + (size_t)0 * 1024 * KSPLIT, 1);
    split_kernel<<<(1024 * 1024) / 256, 256>>>(Wk, Bqkvp + (size_t)1 * 1024 * KSPLIT, 1);
    split_kernel<<<(1024 * 1024) / 256, 256>>>(Wv, Bqkvp + (size_t)2 * 1024 * KSPLIT, 1);
    split_kernel<<<(1024 * 1024) / 256, 256>>>(Wo, Bop, 1);
    bias_concat_kernel<<<12, 256>>>(bq, bk, bv);

    // fused QKV projection -> fp32 [B,H,T,Dh]
    gemm_hmma<<<dim3(3072 / 128, MROWS / 128), 256, GEMM_SMEM>>>(
        A2p, Bqkvp, BIp, nullptr, Qp, Kp, Vp, 1);

    // RoPE + bf16 split conversions
    rope_convert<<<(BHTOT * TSEQ * 32) / 256, 256>>>(Qp, Kp, Qhp, Khp);
    v_convert<<<dim3(TSEQ / 64, BHTOT), 256>>>(Vp, Vtp);

    // HMMA flash attention -> split ctx in g_A2
    attn_mma<<<dim3(TSEQ / AQ, BHTOT), 128, ATTN_SMEM>>>(Qhp, Khp, Vtp, A2p);

    // output projection -> d_out
    gemm_hmma<<<dim3(1024 / 128, MROWS / 128), 256, GEMM_SMEM>>>(
        A2p, Bop, bo, out, nullptr, nullptr, nullptr, 0);

    (void)in_sizes; (void)n_in; (void)out_size;
}

// round 9
// speedup vs baseline: 3.9069x; 1.0453x over previous
#include <cuda_runtime.h>
#include <cuda_bf16.h>
#include <math.h>
#include <stdint.h>

// Problem constants
#define BATCH  2
#define TSEQ   2048
#define DMODEL 1024
#define NHEADS 16
#define HDIM   64
#define BHTOT  (BATCH * NHEADS)     // 32
#define MROWS  (BATCH * TSEQ)       // 4096
#define KROW   2048                 // hi|lo row stride (bf16)

// ---------------------------------------------------------------------------
// Scratch
// ---------------------------------------------------------------------------
__device__ float g_Q[BHTOT * TSEQ * HDIM];     // [B,H,T,Dh] fp32 (pre-rope)
__device__ float g_K[BHTOT * TSEQ * HDIM];
__device__ float g_V[BHTOT * TSEQ * HDIM];
__device__ __nv_bfloat16 g_Qh[(size_t)BHTOT * TSEQ * 128];  // [bh][t][hi64|lo64]
__device__ __nv_bfloat16 g_Kh[(size_t)BHTOT * TSEQ * 128];
__device__ __nv_bfloat16 g_Vt[(size_t)BHTOT * 128 * TSEQ];  // [bh][d'128][t]
__device__ __nv_bfloat16 g_A2[(size_t)MROWS * KROW];      // split activations [hi|lo]
__device__ __nv_bfloat16 g_Bqkv[(size_t)3072 * KROW];     // split Wq|Wk|Wv [hi|lo]
__device__ __nv_bfloat16 g_Bo[(size_t)1024 * KROW];       // split Wo [hi|lo]
__device__ float g_bias_qkv[3072];

// ---------------------------------------------------------------------------
// Helpers
// ---------------------------------------------------------------------------
__device__ __forceinline__ uint32_t smem_u32(const void* p) {
    uint32_t a;
    asm("{ .reg .u64 t; cvta.to.shared.u64 t, %1; cvt.u32.u64 %0, t; }"
        : "=r"(a) : "l"(p));
    return a;
}

#define CP_ASYNC16(sm, gp) \
    asm volatile("cp.async.cg.shared.global [%0], [%1], 16;" :: "r"((uint32_t)(sm)), "l"(gp) : "memory")
#define CP_COMMIT() asm volatile("cp.async.commit_group;" ::: "memory")
#define CP_WAIT(n)  asm volatile("cp.async.wait_group %0;" :: "n"(n) : "memory")

__device__ __forceinline__ void ldsm4(uint32_t* r, uint32_t addr) {
    asm volatile("ldmatrix.sync.aligned.m8n8.x4.shared.b16 {%0,%1,%2,%3}, [%4];"
        : "=r"(r[0]), "=r"(r[1]), "=r"(r[2]), "=r"(r[3]) : "r"(addr));
}

__device__ __forceinline__ void mma_bf16(float* c, const uint32_t* a, const uint32_t* b) {
    asm volatile(
        "mma.sync.aligned.m16n8k16.row.col.f32.bf16.bf16.f32 "
        "{%0,%1,%2,%3}, {%4,%5,%6,%7}, {%8,%9}, {%0,%1,%2,%3};"
        : "+f"(c[0]), "+f"(c[1]), "+f"(c[2]), "+f"(c[3])
        : "r"(a[0]), "r"(a[1]), "r"(a[2]), "r"(a[3]), "r"(b[0]), "r"(b[1]));
}

__device__ __forceinline__ float ex2f(float x) {
    float r; asm("ex2.approx.f32 %0, %1;" : "=f"(r) : "f"(x)); return r;
}

__device__ __forceinline__ uint32_t packbf2(float a, float b) {
    uint32_t r; asm("cvt.rn.bf16x2.f32 %0, %1, %2;" : "=r"(r) : "f"(b), "f"(a)); return r;
}

// swizzles: 16B-chunk XOR within a row
__device__ __forceinline__ uint32_t swz256(int row, int chunk) {     // 256B rows
    return (uint32_t)(row * 256 + ((chunk ^ (row & 7)) << 4));
}
__device__ __forceinline__ uint32_t swz128(int row, int chunk) {     // 128B rows
    return (uint32_t)(row * 128 + ((chunk ^ (row & 7)) << 4));
}

// ---------------------------------------------------------------------------
// Split fp32 -> bf16 [hi | lo] (row stride 2048)
// ---------------------------------------------------------------------------
__global__ void split_kernel(const float* __restrict__ src,
                             __nv_bfloat16* __restrict__ dst)
{
    int idx = blockIdx.x * blockDim.x + threadIdx.x;
    int r = idx >> 10, k = idx & 1023;
    float v = src[idx];
    __nv_bfloat16 hi = __float2bfloat16(v);
    __nv_bfloat16 lo = __float2bfloat16(v - __bfloat162float(hi));
    size_t base = (size_t)r * KROW;
    dst[base + k] = hi;
    dst[base + 1024 + k] = lo;
}

__global__ void bias_concat_kernel(const float* __restrict__ bq,
                                   const float* __restrict__ bk,
                                   const float* __restrict__ bv)
{
    int i = blockIdx.x * blockDim.x + threadIdx.x;   // 3072 total
    const float* s = (i < 1024) ? bq : ((i < 2048) ? bk : bv);
    g_bias_qkv[i] = s[i & 1023];
}

// ---------------------------------------------------------------------------
// HMMA bf16 GEMM: C = x @ W^T + bias via 3-term split over [hi|lo] layout.
// Stage s: term = s/16 (0: hi*hi, 1: lo*hi, 2: hi*lo), sub-chunk = s%16.
// CTA 128x128, 8 warps, BK=64, 3-stage cp.async pipeline, 1 sync/stage.
// ---------------------------------------------------------------------------
#define GNS 48
#define GSTG 3
#define GEMM_SMEM (GSTG * 2 * 128 * 128)   // 98304

__global__ __launch_bounds__(256, 2) void gemm_hmma(
    const __nv_bfloat16* __restrict__ A2, const __nv_bfloat16* __restrict__ B2,
    const float* __restrict__ bias, float* __restrict__ out0,
    float* __restrict__ outQ, float* __restrict__ outK, float* __restrict__ outV,
    int mode)
{
    extern __shared__ __align__(128) char gsm[];
    const uint32_t base = smem_u32(gsm);

    const int tid = threadIdx.x;
    const int lane = tid & 31;
    const int wid = tid >> 5;
    const int warp_m = wid & 3;
    const int warp_n = wid >> 2;
    const int m0 = blockIdx.y * 128;
    const int n0 = blockIdx.x * 128;

    uint32_t sbA[GSTG], sbB[GSTG];
#pragma unroll
    for (int i = 0; i < GSTG; i++) {
        sbA[i] = base + i * 32768;
        sbB[i] = base + i * 32768 + 16384;
    }

    const __nv_bfloat16* Abase = A2 + (size_t)m0 * KROW;
    const __nv_bfloat16* Bbase = B2 + (size_t)n0 * KROW;

    float acc[2][8][4];
#pragma unroll
    for (int i = 0; i < 2; i++)
#pragma unroll
        for (int j = 0; j < 8; j++)
#pragma unroll
            for (int q = 0; q < 4; q++) acc[i][j][q] = 0.f;

    // stage loader: 128 rows x 8 chunks (16B) for A and B from term-dependent cols
    auto load_stage = [&](int s) {
        int b = s % GSTG;
        int term = s >> 4, sub = s & 15;
        int aoff = ((term == 1) ? 1024 : 0) + sub * 64;
        int boff = ((term == 2) ? 1024 : 0) + sub * 64;
        const __nv_bfloat16* Ag = Abase + aoff;
        const __nv_bfloat16* Bg = Bbase + boff;
#pragma unroll
        for (int u = 0; u < 4; u++) {
            int flat = tid + u * 256;            // 0..1023
            int r = flat >> 3, c = flat & 7;
            uint32_t off = swz128(r, c);
            CP_ASYNC16(sbA[b] + off, (const void*)(Ag + (size_t)r * KROW + c * 8));
            CP_ASYNC16(sbB[b] + off, (const void*)(Bg + (size_t)r * KROW + c * 8));
        }
        CP_COMMIT();
    };

    load_stage(0);
    load_stage(1);

    for (int s = 0; s < GNS; s++) {
        int b = s % GSTG;
        if (s < GNS - 1) { CP_WAIT(1); } else { CP_WAIT(0); }
        __syncthreads();

#pragma unroll
        for (int kk = 0; kk < 4; kk++) {
            uint32_t af[2][4];
#pragma unroll
            for (int tm = 0; tm < 2; tm++) {
                int row = warp_m * 32 + tm * 16 + (lane & 7) + ((lane >> 3) & 1) * 8;
                int chunk = kk * 2 + (lane >> 4);
                ldsm4(af[tm], sbA[b] + swz128(row, chunk));
            }
            uint32_t bf[4][4];
#pragma unroll
            for (int p = 0; p < 4; p++) {
                int row = warp_n * 64 + p * 16 + (lane & 7) + (lane >> 4) * 8;
                int chunk = kk * 2 + ((lane >> 3) & 1);
                ldsm4(bf[p], sbB[b] + swz128(row, chunk));
            }
#pragma unroll
            for (int tm = 0; tm < 2; tm++)
#pragma unroll
                for (int tn = 0; tn < 8; tn++)
                    mma_bf16(acc[tm][tn], af[tm], &bf[tn >> 1][(tn & 1) * 2]);
        }

        if (s + 2 < GNS) load_stage(s + 2);
    }

    const int m_base = m0 + warp_m * 32;
    const int n_base = n0 + warp_n * 64;
#pragma unroll
    for (int tm = 0; tm < 2; tm++) {
#pragma unroll
        for (int tn = 0; tn < 8; tn++) {
            int r0 = m_base + tm * 16 + (lane >> 2);
            int c0 = n_base + tn * 8 + 2 * (lane & 3);
            float bx = bias[c0], by = bias[c0 + 1];
#pragma unroll
            for (int half = 0; half < 2; half++) {
                int m = r0 + half * 8;
                float vx = acc[tm][tn][half * 2 + 0] + bx;
                float vy = acc[tm][tn][half * 2 + 1] + by;
                if (mode == 0) {
                    float2* dst = (float2*)(out0 + (size_t)m * 1024 + c0);
                    *dst = make_float2(vx, vy);
                } else {
                    int which = c0 >> 10;
                    int nn = c0 & 1023;
                    int head = nn >> 6;
                    int d0 = nn & 63;
                    int bb2 = m >> 11;
                    int t = m & (TSEQ - 1);
                    float* P = (which == 0) ? outQ : ((which == 1) ? outK : outV);
                    float2* dst = (float2*)(P +
                        (((size_t)(bb2 * NHEADS + head)) * TSEQ + t) * HDIM + d0);
                    *dst = make_float2(vx, vy);
                }
            }
        }
    }
}

// ---------------------------------------------------------------------------
// RoPE + split to bf16 hi/lo. Q gets 0.125*log2(e) folded in (exp2 domain).
// ---------------------------------------------------------------------------
#define QSCALE (0.125f * 1.44269504088896340736f)

__global__ void rope_convert(const float* __restrict__ Q, const float* __restrict__ K,
                             __nv_bfloat16* __restrict__ Qh, __nv_bfloat16* __restrict__ Kh)
{
    int idx = blockIdx.x * blockDim.x + threadIdx.x;   // BHTOT*TSEQ*32
    int d  = idx & 31;
    int t  = (idx >> 5) & (TSEQ - 1);
    int bh = idx >> 16;

    float inv_freq = powf(10000.f, -(float)d * (1.f / 32.f));
    float s, c;
    sincosf((float)t * inv_freq, &s, &c);

    size_t base = ((size_t)bh * TSEQ + t) * HDIM;
    float q1 = Q[base + d], q2 = Q[base + d + 32];
    float k1 = K[base + d], k2 = K[base + d + 32];
    float q1r = (q1 * c - q2 * s) * QSCALE;
    float q2r = (q2 * c + q1 * s) * QSCALE;
    float k1r = k1 * c - k2 * s;
    float k2r = k2 * c + k1 * s;

    size_t ob = ((size_t)bh * TSEQ + t) * 128;
    __nv_bfloat16 h;
    h = __float2bfloat16(q1r); Qh[ob + d] = h;
    Qh[ob + 64 + d] = __float2bfloat16(q1r - __bfloat162float(h));
    h = __float2bfloat16(q2r); Qh[ob + 32 + d] = h;
    Qh[ob + 96 + d] = __float2bfloat16(q2r - __bfloat162float(h));
    h = __float2bfloat16(k1r); Kh[ob + d] = h;
    Kh[ob + 64 + d] = __float2bfloat16(k1r - __bfloat162float(h));
    h = __float2bfloat16(k2r); Kh[ob + 32 + d] = h;
    Kh[ob + 96 + d] = __float2bfloat16(k2r - __bfloat162float(h));
}

// ---------------------------------------------------------------------------
// V transpose + split
// ---------------------------------------------------------------------------
__global__ void v_convert(const float* __restrict__ V, __nv_bfloat16* __restrict__ Vt)
{
    __shared__ float tile[64][65];
    int bh = blockIdx.y;
    int t0 = blockIdx.x * 64;
    int tid = threadIdx.x;   // 256
#pragma unroll
    for (int i = 0; i < 16; i++) {
        int flat = tid + i * 256;
        int r = flat >> 6, d = flat & 63;
        tile[r][d] = V[((size_t)bh * TSEQ + t0 + r) * HDIM + d];
    }
    __syncthreads();
#pragma unroll
    for (int i = 0; i < 16; i++) {
        int flat = tid + i * 256;
        int d = flat >> 6, c = flat & 63;
        float v = tile[c][d];
        __nv_bfloat16 h = __float2bfloat16(v);
        Vt[((size_t)bh * 128 + d) * TSEQ + t0 + c] = h;
        Vt[((size_t)bh * 128 + 64 + d) * TSEQ + t0 + c] =
            __float2bfloat16(v - __bfloat162float(h));
    }
}

// ---------------------------------------------------------------------------
// HMMA flash attention with fragment-reuse term scheduling.
// QK: phase A (K_hi: Q_hi + Q_lo terms), phase B (K_lo: Q_hi term).
// PV: phase A (V_hi: P_hi + P_lo terms), phase B (V_lo: P_hi term).
// ---------------------------------------------------------------------------
#define AQ 128
#define AK 64
#define NKT (TSEQ / AK)   // 32
#define ATTN_SMEM 98304

__global__ __launch_bounds__(128) void attn_mma(
    const __nv_bfloat16* __restrict__ Qh, const __nv_bfloat16* __restrict__ Kh,
    const __nv_bfloat16* __restrict__ Vt, __nv_bfloat16* __restrict__ A2)
{
    extern __shared__ __align__(128) char smem[];
    const uint32_t sQ = smem_u32(smem);
    const uint32_t sK[2] = { sQ + 32768, sQ + 32768 + 16384 };
    const uint32_t sV[2] = { sQ + 65536, sQ + 65536 + 16384 };

    const int tid = threadIdx.x, lane = tid & 31, wid = tid >> 5;
    const int qtile = blockIdx.x, bh = blockIdx.y;

    const __nv_bfloat16* Qg = Qh + ((size_t)bh * TSEQ + qtile * AQ) * 128;
    const __nv_bfloat16* Kg = Kh + (size_t)bh * TSEQ * 128;
    const __nv_bfloat16* Vg = Vt + (size_t)bh * 128 * TSEQ;

    auto loadKV = [&](int t) {
        int b = t & 1;
        const __nv_bfloat16* Kt = Kg + (size_t)t * AK * 128;
#pragma unroll
        for (int u = 0; u < 8; u++) {
            int flat = tid + u * 128;
            int r = flat >> 4, c = flat & 15;
            CP_ASYNC16(sK[b] + swz256(r, c), (const void*)(Kt + r * 128 + c * 8));
        }
        const __nv_bfloat16* Vtt = Vg + t * AK;
#pragma unroll
        for (int u = 0; u < 8; u++) {
            int flat = tid + u * 128;
            int r = flat >> 3, c = flat & 7;
            CP_ASYNC16(sV[b] + swz128(r, c), (const void*)(Vtt + (size_t)r * TSEQ + c * 8));
        }
    };

#pragma unroll
    for (int u = 0; u < 16; u++) {
        int flat = tid + u * 128;
        int r = flat >> 4, c = flat & 15;
        CP_ASYNC16(sQ + swz256(r, c), (const void*)(Qg + r * 128 + c * 8));
    }
    loadKV(0);
    CP_COMMIT();

    float O[2][8][4];
#pragma unroll
    for (int i = 0; i < 2; i++)
#pragma unroll
        for (int j = 0; j < 8; j++)
#pragma unroll
            for (int q = 0; q < 4; q++) O[i][j][q] = 0.f;
    float mrow[2][2] = { {-1e30f, -1e30f}, {-1e30f, -1e30f} };
    float lrow[2][2] = { {0.f, 0.f}, {0.f, 0.f} };

    for (int t = 0; t < NKT; t++) {
        int b = t & 1;
        if (t + 1 < NKT) { loadKV(t + 1); CP_COMMIT(); CP_WAIT(1); }
        else { CP_WAIT(0); }
        __syncthreads();

        float S[2][8][4];
#pragma unroll
        for (int i = 0; i < 2; i++)
#pragma unroll
            for (int j = 0; j < 8; j++)
#pragma unroll
                for (int q = 0; q < 4; q++) S[i][j][q] = 0.f;

        // ---- QK phase A: K_hi with Q_hi and Q_lo ----
#pragma unroll
        for (int kk = 0; kk < 4; kk++) {
            uint32_t bf4[4][4];
#pragma unroll
            for (int p = 0; p < 4; p++) {
                int row = p * 16 + (lane & 7) + (lane >> 4) * 8;
                int chunk = kk * 2 + ((lane >> 3) & 1);
                ldsm4(bf4[p], sK[b] + swz256(row, chunk));
            }
            uint32_t afh[2][4], afl[2][4];
#pragma unroll
            for (int tm = 0; tm < 2; tm++) {
                int row = wid * 32 + tm * 16 + (lane & 7) + ((lane >> 3) & 1) * 8;
                int chunk = kk * 2 + (lane >> 4);
                ldsm4(afh[tm], sQ + swz256(row, chunk));
                ldsm4(afl[tm], sQ + swz256(row, 8 + chunk));
            }
#pragma unroll
            for (int tm = 0; tm < 2; tm++)
#pragma unroll
                for (int tn = 0; tn < 8; tn++) {
                    const uint32_t* bb = &bf4[tn >> 1][(tn & 1) * 2];
                    mma_bf16(S[tm][tn], afh[tm], bb);
                    mma_bf16(S[tm][tn], afl[tm], bb);
                }
        }
        // ---- QK phase B: K_lo with Q_hi ----
#pragma unroll
        for (int kk = 0; kk < 4; kk++) {
            uint32_t bf4[4][4];
#pragma unroll
            for (int p = 0; p < 4; p++) {
                int row = p * 16 + (lane & 7) + (lane >> 4) * 8;
                int chunk = 8 + kk * 2 + ((lane >> 3) & 1);
                ldsm4(bf4[p], sK[b] + swz256(row, chunk));
            }
            uint32_t afh[2][4];
#pragma unroll
            for (int tm = 0; tm < 2; tm++) {
                int row = wid * 32 + tm * 16 + (lane & 7) + ((lane >> 3) & 1) * 8;
                int chunk = kk * 2 + (lane >> 4);
                ldsm4(afh[tm], sQ + swz256(row, chunk));
            }
#pragma unroll
            for (int tm = 0; tm < 2; tm++)
#pragma unroll
                for (int tn = 0; tn < 8; tn++)
                    mma_bf16(S[tm][tn], afh[tm], &bf4[tn >> 1][(tn & 1) * 2]);
        }

        // ---- online softmax (exp2 domain) + P pack ----
        uint32_t Ppk[2][2][16];
#pragma unroll
        for (int tm = 0; tm < 2; tm++) {
#pragma unroll
            for (int rh = 0; rh < 2; rh++) {
                float mx = S[tm][0][rh * 2];
#pragma unroll
                for (int tn = 0; tn < 8; tn++) {
                    mx = fmaxf(mx, S[tm][tn][rh * 2 + 0]);
                    mx = fmaxf(mx, S[tm][tn][rh * 2 + 1]);
                }
                mx = fmaxf(mx, __shfl_xor_sync(0xffffffffu, mx, 1));
                mx = fmaxf(mx, __shfl_xor_sync(0xffffffffu, mx, 2));
                float mold = mrow[tm][rh];
                float mnew = fmaxf(mold, mx);
                float corr = ex2f(mold - mnew);
                mrow[tm][rh] = mnew;
                float rsum = 0.f;
#pragma unroll
                for (int tn = 0; tn < 8; tn++) {
                    float p0 = ex2f(S[tm][tn][rh * 2 + 0] - mnew);
                    float p1 = ex2f(S[tm][tn][rh * 2 + 1] - mnew);
                    rsum += p0 + p1;
                    float h0 = __bfloat162float(__float2bfloat16(p0));
                    float h1 = __bfloat162float(__float2bfloat16(p1));
                    Ppk[tm][0][tn * 2 + rh] = packbf2(p0, p1);
                    Ppk[tm][1][tn * 2 + rh] = packbf2(p0 - h0, p1 - h1);
                    O[tm][tn][rh * 2 + 0] *= corr;
                    O[tm][tn][rh * 2 + 1] *= corr;
                }
                rsum += __shfl_xor_sync(0xffffffffu, rsum, 1);
                rsum += __shfl_xor_sync(0xffffffffu, rsum, 2);
                lrow[tm][rh] = lrow[tm][rh] * corr + rsum;
            }
        }

        // ---- PV phase A: V_hi with P_hi and P_lo ----
#pragma unroll
        for (int kk = 0; kk < 4; kk++) {
            uint32_t bfv[4][4];
#pragma unroll
            for (int p = 0; p < 4; p++) {
                int row = p * 16 + (lane & 7) + (lane >> 4) * 8;
                int chunk = kk * 2 + ((lane >> 3) & 1);
                ldsm4(bfv[p], sV[b] + swz128(row, chunk));
            }
#pragma unroll
            for (int tm = 0; tm < 2; tm++)
#pragma unroll
                for (int tn = 0; tn < 8; tn++) {
                    const uint32_t* bb = &bfv[tn >> 1][(tn & 1) * 2];
                    mma_bf16(O[tm][tn], &Ppk[tm][0][4 * kk], bb);
                    mma_bf16(O[tm][tn], &Ppk[tm][1][4 * kk], bb);
                }
        }
        // ---- PV phase B: V_lo with P_hi ----
#pragma unroll
        for (int kk = 0; kk < 4; kk++) {
            uint32_t bfv[4][4];
#pragma unroll
            for (int p = 0; p < 4; p++) {
                int row = 64 + p * 16 + (lane & 7) + (lane >> 4) * 8;
                int chunk = kk * 2 + ((lane >> 3) & 1);
                ldsm4(bfv[p], sV[b] + swz128(row, chunk));
            }
#pragma unroll
            for (int tm = 0; tm < 2; tm++)
#pragma unroll
                for (int tn = 0; tn < 8; tn++)
                    mma_bf16(O[tm][tn], &Ppk[tm][0][4 * kk],
                             &bfv[tn >> 1][(tn & 1) * 2]);
        }
        __syncthreads();
    }

    // ---- epilogue: write split ctx [hi|lo] into A2 ----
    const int bb = bh >> 4, h = bh & 15;
#pragma unroll
    for (int tm = 0; tm < 2; tm++) {
#pragma unroll
        for (int rh = 0; rh < 2; rh++) {
            float inv = 1.f / lrow[tm][rh];
            int trow = qtile * AQ + wid * 32 + tm * 16 + rh * 8 + (lane >> 2);
            size_t m = (size_t)bb * TSEQ + trow;
            __nv_bfloat16* rowp = A2 + m * KROW + h * 64;
#pragma unroll
            for (int tn = 0; tn < 8; tn++) {
                float o0 = O[tm][tn][rh * 2 + 0] * inv;
                float o1 = O[tm][tn][rh * 2 + 1] * inv;
                int d = tn * 8 + (lane & 3) * 2;
                uint32_t hi2 = packbf2(o0, o1);
                float h0 = __bfloat162float(__float2bfloat16(o0));
                float h1 = __bfloat162float(__float2bfloat16(o1));
                uint32_t lo2 = packbf2(o0 - h0, o1 - h1);
                *(uint32_t*)(rowp + d) = hi2;
                *(uint32_t*)(rowp + 1024 + d) = lo2;
            }
        }
    }
}

// ---------------------------------------------------------------------------
// Launch
// ---------------------------------------------------------------------------
extern "C" void kernel_launch(void* const* d_in, const int* in_sizes, int n_in,
                              void* d_out, int out_size)
{
    const float* x  = (const float*)d_in[0];
    const float* Wq = (const float*)d_in[1];
    const float* bq = (const float*)d_in[2];
    const float* Wk = (const float*)d_in[3];
    const float* bk = (const float*)d_in[4];
    const float* Wv = (const float*)d_in[5];
    const float* bv = (const float*)d_in[6];
    const float* Wo = (const float*)d_in[7];
    const float* bo = (const float*)d_in[8];
    float* out = (float*)d_out;

    float *Qp, *Kp, *Vp, *BIp;
    __nv_bfloat16 *A2p, *Bqkvp, *Bop, *Qhp, *Khp, *Vtp;
    cudaGetSymbolAddress((void**)&Qp, g_Q);
    cudaGetSymbolAddress((void**)&Kp, g_K);
    cudaGetSymbolAddress((void**)&Vp, g_V);
    cudaGetSymbolAddress((void**)&A2p, g_A2);
    cudaGetSymbolAddress((void**)&Bqkvp, g_Bqkv);
    cudaGetSymbolAddress((void**)&Bop, g_Bo);
    cudaGetSymbolAddress((void**)&BIp, g_bias_qkv);
    cudaGetSymbolAddress((void**)&Qhp, g_Qh);
    cudaGetSymbolAddress((void**)&Khp, g_Kh);
    cudaGetSymbolAddress((void**)&Vtp, g_Vt);

    cudaFuncSetAttribute(attn_mma, cudaFuncAttributeMaxDynamicSharedMemorySize, ATTN_SMEM);
    cudaFuncSetAttribute(gemm_hmma, cudaFuncAttributeMaxDynamicSharedMemorySize, GEMM_SMEM);

    // split conversions (hi|lo)
    split_kernel<<<(MROWS * 1024) / 256, 256>>>(x, A2p);
    split_kernel<<<(1024 * 1024) / 256, 256>>>(Wq, Bqkvp + (size_t)0 * 1024 * KROW);
    split_kernel<<<(1024 * 1024) / 256, 256>>>(Wk, Bqkvp + (size_t)1 * 1024 * KROW);
    split_kernel<<<(1024 * 1024) / 256, 256>>>(Wv, Bqkvp + (size_t)2 * 1024 * KROW);
    split_kernel<<<(1024 * 1024) / 256, 256>>>(Wo, Bop);
    bias_concat_kernel<<<12, 256>>>(bq, bk, bv);

    // fused QKV projection -> fp32 [B,H,T,Dh]
    gemm_hmma<<<dim3(3072 / 128, MROWS / 128), 256, GEMM_SMEM>>>(
        A2p, Bqkvp, BIp, nullptr, Qp, Kp, Vp, 1);

    // RoPE + bf16 split conversions
    rope_convert<<<(BHTOT * TSEQ * 32) / 256, 256>>>(Qp, Kp, Qhp, Khp);
    v_convert<<<dim3(TSEQ / 64, BHTOT), 256>>>(Vp, Vtp);

    // HMMA flash attention -> split ctx in g_A2
    attn_mma<<<dim3(TSEQ / AQ, BHTOT), 128, ATTN_SMEM>>>(Qhp, Khp, Vtp, A2p);

    // output projection -> d_out
    gemm_hmma<<<dim3(1024 / 128, MROWS / 128), 256, GEMM_SMEM>>>(
        A2p, Bop, bo, out, nullptr, nullptr, nullptr, 0);

    (void)in_sizes; (void)n_in; (void)out_size;
}

// round 10
// speedup vs baseline: 3.9314x; 1.0063x over previous
#include <cuda_runtime.h>
#include <cuda_bf16.h>
#include <math.h>
#include <stdint.h>

// Problem constants
#define BATCH  2
#define TSEQ   2048
#define DMODEL 1024
#define NHEADS 16
#define HDIM   64
#define BHTOT  (BATCH * NHEADS)     // 32
#define MROWS  (BATCH * TSEQ)       // 4096
#define KROW   2048                 // hi|lo row stride (bf16)

// ---------------------------------------------------------------------------
// Scratch
// ---------------------------------------------------------------------------
__device__ float g_Q[BHTOT * TSEQ * HDIM];     // [B,H,T,Dh] fp32 (pre-rope)
__device__ float g_K[BHTOT * TSEQ * HDIM];
__device__ float g_V[BHTOT * TSEQ * HDIM];
__device__ __nv_bfloat16 g_Qh[(size_t)BHTOT * TSEQ * 128];  // [bh][t][hi64|lo64]
__device__ __nv_bfloat16 g_Kh[(size_t)BHTOT * TSEQ * 128];
__device__ __nv_bfloat16 g_Vt[(size_t)BHTOT * 128 * TSEQ];  // [bh][d'128][t]
__device__ __nv_bfloat16 g_A2[(size_t)MROWS * KROW];      // split activations [hi|lo]
__device__ __nv_bfloat16 g_Bqkv[(size_t)3072 * KROW];     // split Wq|Wk|Wv [hi|lo]
__device__ __nv_bfloat16 g_Bo[(size_t)1024 * KROW];       // split Wo [hi|lo]
__device__ float g_bias_qkv[3072];
__device__ float2 g_trig[TSEQ * 32];                      // cos/sin table [t][d]

// ---------------------------------------------------------------------------
// Helpers
// ---------------------------------------------------------------------------
__device__ __forceinline__ uint32_t smem_u32(const void* p) {
    uint32_t a;
    asm("{ .reg .u64 t; cvta.to.shared.u64 t, %1; cvt.u32.u64 %0, t; }"
        : "=r"(a) : "l"(p));
    return a;
}

#define CP_ASYNC16(sm, gp) \
    asm volatile("cp.async.cg.shared.global [%0], [%1], 16;" :: "r"((uint32_t)(sm)), "l"(gp) : "memory")
#define CP_COMMIT() asm volatile("cp.async.commit_group;" ::: "memory")
#define CP_WAIT(n)  asm volatile("cp.async.wait_group %0;" :: "n"(n) : "memory")

__device__ __forceinline__ void ldsm4(uint32_t* r, uint32_t addr) {
    asm volatile("ldmatrix.sync.aligned.m8n8.x4.shared.b16 {%0,%1,%2,%3}, [%4];"
        : "=r"(r[0]), "=r"(r[1]), "=r"(r[2]), "=r"(r[3]) : "r"(addr));
}

__device__ __forceinline__ void mma_bf16(float* c, const uint32_t* a, const uint32_t* b) {
    asm volatile(
        "mma.sync.aligned.m16n8k16.row.col.f32.bf16.bf16.f32 "
        "{%0,%1,%2,%3}, {%4,%5,%6,%7}, {%8,%9}, {%0,%1,%2,%3};"
        : "+f"(c[0]), "+f"(c[1]), "+f"(c[2]), "+f"(c[3])
        : "r"(a[0]), "r"(a[1]), "r"(a[2]), "r"(a[3]), "r"(b[0]), "r"(b[1]));
}

__device__ __forceinline__ float ex2f(float x) {
    float r; asm("ex2.approx.f32 %0, %1;" : "=f"(r) : "f"(x)); return r;
}

__device__ __forceinline__ uint32_t packbf2(float a, float b) {
    uint32_t r; asm("cvt.rn.bf16x2.f32 %0, %1, %2;" : "=r"(r) : "f"(b), "f"(a)); return r;
}

// swizzles: 16B-chunk XOR within a row
__device__ __forceinline__ uint32_t swz256(int row, int chunk) {     // 256B rows
    return (uint32_t)(row * 256 + ((chunk ^ (row & 7)) << 4));
}
__device__ __forceinline__ uint32_t swz128(int row, int chunk) {     // 128B rows
    return (uint32_t)(row * 128 + ((chunk ^ (row & 7)) << 4));
}

// ---------------------------------------------------------------------------
// trig table: g_trig[t*32+d] = (cos, sin)(t * 10000^{-d/32})
// ---------------------------------------------------------------------------
__global__ void trig_kernel()
{
    int idx = blockIdx.x * blockDim.x + threadIdx.x;   // 65536
    int t = idx >> 5, d = idx & 31;
    float inv_freq = powf(10000.f, -(float)d * (1.f / 32.f));
    float s, c;
    sincosf((float)t * inv_freq, &s, &c);
    g_trig[idx] = make_float2(c, s);
}

// ---------------------------------------------------------------------------
// Fused split: x, Wq, Wk, Wv, Wo -> [hi|lo] bf16 layouts, + bias concat tail.
// rows: [0,4096) x -> A2 ; [4096,5120) Wq ; [5120,6144) Wk ; [6144,7168) Wv ;
//       [7168,8192) Wo -> Bo. blocks >= 32768: bias concat (12 blocks).
// ---------------------------------------------------------------------------
__global__ void split_all(const float* __restrict__ x,
                          const float* __restrict__ Wq, const float* __restrict__ Wk,
                          const float* __restrict__ Wv, const float* __restrict__ Wo,
                          const float* __restrict__ bq, const float* __restrict__ bk,
                          const float* __restrict__ bv,
                          __nv_bfloat16* __restrict__ A2,
                          __nv_bfloat16* __restrict__ Bqkv,
                          __nv_bfloat16* __restrict__ Bo)
{
    int bid = blockIdx.x;
    int tid = threadIdx.x;
    if (bid >= 32768) {                       // bias tail: 12 blocks x 256 = 3072
        int i = (bid - 32768) * 256 + tid;
        const float* s = (i < 1024) ? bq : ((i < 2048) ? bk : bv);
        g_bias_qkv[i] = s[i & 1023];
        return;
    }
    int idx = bid * 256 + tid;
    int row = idx >> 10, k = idx & 1023;
    const float* src;
    __nv_bfloat16* dst;
    int lrow;
    if (row < 4096)      { src = x;  dst = A2;                          lrow = row; }
    else if (row < 5120) { src = Wq; dst = Bqkv;                        lrow = row - 4096; }
    else if (row < 6144) { src = Wk; dst = Bqkv + (size_t)1024 * KROW;  lrow = row - 5120; }
    else if (row < 7168) { src = Wv; dst = Bqkv + (size_t)2048 * KROW;  lrow = row - 6144; }
    else                 { src = Wo; dst = Bo;                          lrow = row - 7168; }
    float v = src[(size_t)lrow * 1024 + k];
    __nv_bfloat16 hi = __float2bfloat16(v);
    __nv_bfloat16 lo = __float2bfloat16(v - __bfloat162float(hi));
    size_t base = (size_t)lrow * KROW;
    dst[base + k] = hi;
    dst[base + 1024 + k] = lo;
}

// ---------------------------------------------------------------------------
// HMMA bf16 GEMM: C = x @ W^T + bias via 3-term split over [hi|lo] layout.
// Stage s: term = s/16 (0: hi*hi, 1: lo*hi, 2: hi*lo), sub-chunk = s%16.
// CTA 128x128, 8 warps, BK=64, 3-stage cp.async pipeline, 1 sync/stage.
// ---------------------------------------------------------------------------
#define GNS 48
#define GSTG 3
#define GEMM_SMEM (GSTG * 2 * 128 * 128)   // 98304

__global__ __launch_bounds__(256, 2) void gemm_hmma(
    const __nv_bfloat16* __restrict__ A2, const __nv_bfloat16* __restrict__ B2,
    const float* __restrict__ bias, float* __restrict__ out0,
    float* __restrict__ outQ, float* __restrict__ outK, float* __restrict__ outV,
    int mode)
{
    extern __shared__ __align__(128) char gsm[];
    const uint32_t base = smem_u32(gsm);

    const int tid = threadIdx.x;
    const int lane = tid & 31;
    const int wid = tid >> 5;
    const int warp_m = wid & 3;
    const int warp_n = wid >> 2;
    const int m0 = blockIdx.y * 128;
    const int n0 = blockIdx.x * 128;

    uint32_t sbA[GSTG], sbB[GSTG];
#pragma unroll
    for (int i = 0; i < GSTG; i++) {
        sbA[i] = base + i * 32768;
        sbB[i] = base + i * 32768 + 16384;
    }

    const __nv_bfloat16* Abase = A2 + (size_t)m0 * KROW;
    const __nv_bfloat16* Bbase = B2 + (size_t)n0 * KROW;

    float acc[2][8][4];
#pragma unroll
    for (int i = 0; i < 2; i++)
#pragma unroll
        for (int j = 0; j < 8; j++)
#pragma unroll
            for (int q = 0; q < 4; q++) acc[i][j][q] = 0.f;

    auto load_stage = [&](int s) {
        int b = s % GSTG;
        int term = s >> 4, sub = s & 15;
        int aoff = ((term == 1) ? 1024 : 0) + sub * 64;
        int boff = ((term == 2) ? 1024 : 0) + sub * 64;
        const __nv_bfloat16* Ag = Abase + aoff;
        const __nv_bfloat16* Bg = Bbase + boff;
#pragma unroll
        for (int u = 0; u < 4; u++) {
            int flat = tid + u * 256;            // 0..1023
            int r = flat >> 3, c = flat & 7;
            uint32_t off = swz128(r, c);
            CP_ASYNC16(sbA[b] + off, (const void*)(Ag + (size_t)r * KROW + c * 8));
            CP_ASYNC16(sbB[b] + off, (const void*)(Bg + (size_t)r * KROW + c * 8));
        }
        CP_COMMIT();
    };

    load_stage(0);
    load_stage(1);

    for (int s = 0; s < GNS; s++) {
        int b = s % GSTG;
        if (s < GNS - 1) { CP_WAIT(1); } else { CP_WAIT(0); }
        __syncthreads();

#pragma unroll
        for (int kk = 0; kk < 4; kk++) {
            uint32_t af[2][4];
#pragma unroll
            for (int tm = 0; tm < 2; tm++) {
                int row = warp_m * 32 + tm * 16 + (lane & 7) + ((lane >> 3) & 1) * 8;
                int chunk = kk * 2 + (lane >> 4);
                ldsm4(af[tm], sbA[b] + swz128(row, chunk));
            }
            uint32_t bf[4][4];
#pragma unroll
            for (int p = 0; p < 4; p++) {
                int row = warp_n * 64 + p * 16 + (lane & 7) + (lane >> 4) * 8;
                int chunk = kk * 2 + ((lane >> 3) & 1);
                ldsm4(bf[p], sbB[b] + swz128(row, chunk));
            }
#pragma unroll
            for (int tm = 0; tm < 2; tm++)
#pragma unroll
                for (int tn = 0; tn < 8; tn++)
                    mma_bf16(acc[tm][tn], af[tm], &bf[tn >> 1][(tn & 1) * 2]);
        }

        if (s + 2 < GNS) load_stage(s + 2);
    }

    const int m_base = m0 + warp_m * 32;
    const int n_base = n0 + warp_n * 64;
#pragma unroll
    for (int tm = 0; tm < 2; tm++) {
#pragma unroll
        for (int tn = 0; tn < 8; tn++) {
            int r0 = m_base + tm * 16 + (lane >> 2);
            int c0 = n_base + tn * 8 + 2 * (lane & 3);
            float bx = bias[c0], by = bias[c0 + 1];
#pragma unroll
            for (int half = 0; half < 2; half++) {
                int m = r0 + half * 8;
                float vx = acc[tm][tn][half * 2 + 0] + bx;
                float vy = acc[tm][tn][half * 2 + 1] + by;
                if (mode == 0) {
                    float2* dst = (float2*)(out0 + (size_t)m * 1024 + c0);
                    *dst = make_float2(vx, vy);
                } else {
                    int which = c0 >> 10;
                    int nn = c0 & 1023;
                    int head = nn >> 6;
                    int d0 = nn & 63;
                    int bb2 = m >> 11;
                    int t = m & (TSEQ - 1);
                    float* P = (which == 0) ? outQ : ((which == 1) ? outK : outV);
                    float2* dst = (float2*)(P +
                        (((size_t)(bb2 * NHEADS + head)) * TSEQ + t) * HDIM + d0);
                    *dst = make_float2(vx, vy);
                }
            }
        }
    }
}

// ---------------------------------------------------------------------------
// RoPE + split to bf16 hi/lo (table-based). Q gets 0.125*log2(e) folded in.
// ---------------------------------------------------------------------------
#define QSCALE (0.125f * 1.44269504088896340736f)

__global__ void rope_convert(const float* __restrict__ Q, const float* __restrict__ K,
                             __nv_bfloat16* __restrict__ Qh, __nv_bfloat16* __restrict__ Kh)
{
    int idx = blockIdx.x * blockDim.x + threadIdx.x;   // BHTOT*TSEQ*32
    int d  = idx & 31;
    int t  = (idx >> 5) & (TSEQ - 1);
    int bh = idx >> 16;

    float2 cs = g_trig[(t << 5) + d];
    float c = cs.x, s = cs.y;

    size_t base = ((size_t)bh * TSEQ + t) * HDIM;
    float q1 = Q[base + d], q2 = Q[base + d + 32];
    float k1 = K[base + d], k2 = K[base + d + 32];
    float q1r = (q1 * c - q2 * s) * QSCALE;
    float q2r = (q2 * c + q1 * s) * QSCALE;
    float k1r = k1 * c - k2 * s;
    float k2r = k2 * c + k1 * s;

    size_t ob = ((size_t)bh * TSEQ + t) * 128;
    __nv_bfloat16 h;
    h = __float2bfloat16(q1r); Qh[ob + d] = h;
    Qh[ob + 64 + d] = __float2bfloat16(q1r - __bfloat162float(h));
    h = __float2bfloat16(q2r); Qh[ob + 32 + d] = h;
    Qh[ob + 96 + d] = __float2bfloat16(q2r - __bfloat162float(h));
    h = __float2bfloat16(k1r); Kh[ob + d] = h;
    Kh[ob + 64 + d] = __float2bfloat16(k1r - __bfloat162float(h));
    h = __float2bfloat16(k2r); Kh[ob + 32 + d] = h;
    Kh[ob + 96 + d] = __float2bfloat16(k2r - __bfloat162float(h));
}

// ---------------------------------------------------------------------------
// V transpose + split
// ---------------------------------------------------------------------------
__global__ void v_convert(const float* __restrict__ V, __nv_bfloat16* __restrict__ Vt)
{
    __shared__ float tile[64][65];
    int bh = blockIdx.y;
    int t0 = blockIdx.x * 64;
    int tid = threadIdx.x;   // 256
#pragma unroll
    for (int i = 0; i < 16; i++) {
        int flat = tid + i * 256;
        int r = flat >> 6, d = flat & 63;
        tile[r][d] = V[((size_t)bh * TSEQ + t0 + r) * HDIM + d];
    }
    __syncthreads();
#pragma unroll
    for (int i = 0; i < 16; i++) {
        int flat = tid + i * 256;
        int d = flat >> 6, c = flat & 63;
        float v = tile[c][d];
        __nv_bfloat16 h = __float2bfloat16(v);
        Vt[((size_t)bh * 128 + d) * TSEQ + t0 + c] = h;
        Vt[((size_t)bh * 128 + 64 + d) * TSEQ + t0 + c] =
            __float2bfloat16(v - __bfloat162float(h));
    }
}

// ---------------------------------------------------------------------------
// HMMA flash attention with fragment-reuse term scheduling (unchanged R8).
// ---------------------------------------------------------------------------
#define AQ 128
#define AK 64
#define NKT (TSEQ / AK)   // 32
#define ATTN_SMEM 98304

__global__ __launch_bounds__(128) void attn_mma(
    const __nv_bfloat16* __restrict__ Qh, const __nv_bfloat16* __restrict__ Kh,
    const __nv_bfloat16* __restrict__ Vt, __nv_bfloat16* __restrict__ A2)
{
    extern __shared__ __align__(128) char smem[];
    const uint32_t sQ = smem_u32(smem);
    const uint32_t sK[2] = { sQ + 32768, sQ + 32768 + 16384 };
    const uint32_t sV[2] = { sQ + 65536, sQ + 65536 + 16384 };

    const int tid = threadIdx.x, lane = tid & 31, wid = tid >> 5;
    const int qtile = blockIdx.x, bh = blockIdx.y;

    const __nv_bfloat16* Qg = Qh + ((size_t)bh * TSEQ + qtile * AQ) * 128;
    const __nv_bfloat16* Kg = Kh + (size_t)bh * TSEQ * 128;
    const __nv_bfloat16* Vg = Vt + (size_t)bh * 128 * TSEQ;

    auto loadKV = [&](int t) {
        int b = t & 1;
        const __nv_bfloat16* Kt = Kg + (size_t)t * AK * 128;
#pragma unroll
        for (int u = 0; u < 8; u++) {
            int flat = tid + u * 128;
            int r = flat >> 4, c = flat & 15;
            CP_ASYNC16(sK[b] + swz256(r, c), (const void*)(Kt + r * 128 + c * 8));
        }
        const __nv_bfloat16* Vtt = Vg + t * AK;
#pragma unroll
        for (int u = 0; u < 8; u++) {
            int flat = tid + u * 128;
            int r = flat >> 3, c = flat & 7;
            CP_ASYNC16(sV[b] + swz128(r, c), (const void*)(Vtt + (size_t)r * TSEQ + c * 8));
        }
    };

#pragma unroll
    for (int u = 0; u < 16; u++) {
        int flat = tid + u * 128;
        int r = flat >> 4, c = flat & 15;
        CP_ASYNC16(sQ + swz256(r, c), (const void*)(Qg + r * 128 + c * 8));
    }
    loadKV(0);
    CP_COMMIT();

    float O[2][8][4];
#pragma unroll
    for (int i = 0; i < 2; i++)
#pragma unroll
        for (int j = 0; j < 8; j++)
#pragma unroll
            for (int q = 0; q < 4; q++) O[i][j][q] = 0.f;
    float mrow[2][2] = { {-1e30f, -1e30f}, {-1e30f, -1e30f} };
    float lrow[2][2] = { {0.f, 0.f}, {0.f, 0.f} };

    for (int t = 0; t < NKT; t++) {
        int b = t & 1;
        if (t + 1 < NKT) { loadKV(t + 1); CP_COMMIT(); CP_WAIT(1); }
        else { CP_WAIT(0); }
        __syncthreads();

        float S[2][8][4];
#pragma unroll
        for (int i = 0; i < 2; i++)
#pragma unroll
            for (int j = 0; j < 8; j++)
#pragma unroll
                for (int q = 0; q < 4; q++) S[i][j][q] = 0.f;

        // ---- QK phase A: K_hi with Q_hi and Q_lo ----
#pragma unroll
        for (int kk = 0; kk < 4; kk++) {
            uint32_t bf4[4][4];
#pragma unroll
            for (int p = 0; p < 4; p++) {
                int row = p * 16 + (lane & 7) + (lane >> 4) * 8;
                int chunk = kk * 2 + ((lane >> 3) & 1);
                ldsm4(bf4[p], sK[b] + swz256(row, chunk));
            }
            uint32_t afh[2][4], afl[2][4];
#pragma unroll
            for (int tm = 0; tm < 2; tm++) {
                int row = wid * 32 + tm * 16 + (lane & 7) + ((lane >> 3) & 1) * 8;
                int chunk = kk * 2 + (lane >> 4);
                ldsm4(afh[tm], sQ + swz256(row, chunk));
                ldsm4(afl[tm], sQ + swz256(row, 8 + chunk));
            }
#pragma unroll
            for (int tm = 0; tm < 2; tm++)
#pragma unroll
                for (int tn = 0; tn < 8; tn++) {
                    const uint32_t* bb = &bf4[tn >> 1][(tn & 1) * 2];
                    mma_bf16(S[tm][tn], afh[tm], bb);
                    mma_bf16(S[tm][tn], afl[tm], bb);
                }
        }
        // ---- QK phase B: K_lo with Q_hi ----
#pragma unroll
        for (int kk = 0; kk < 4; kk++) {
            uint32_t bf4[4][4];
#pragma unroll
            for (int p = 0; p < 4; p++) {
                int row = p * 16 + (lane & 7) + (lane >> 4) * 8;
                int chunk = 8 + kk * 2 + ((lane >> 3) & 1);
                ldsm4(bf4[p], sK[b] + swz256(row, chunk));
            }
            uint32_t afh[2][4];
#pragma unroll
            for (int tm = 0; tm < 2; tm++) {
                int row = wid * 32 + tm * 16 + (lane & 7) + ((lane >> 3) & 1) * 8;
                int chunk = kk * 2 + (lane >> 4);
                ldsm4(afh[tm], sQ + swz256(row, chunk));
            }
#pragma unroll
            for (int tm = 0; tm < 2; tm++)
#pragma unroll
                for (int tn = 0; tn < 8; tn++)
                    mma_bf16(S[tm][tn], afh[tm], &bf4[tn >> 1][(tn & 1) * 2]);
        }

        // ---- online softmax (exp2 domain) + P pack ----
        uint32_t Ppk[2][2][16];
#pragma unroll
        for (int tm = 0; tm < 2; tm++) {
#pragma unroll
            for (int rh = 0; rh < 2; rh++) {
                float mx = S[tm][0][rh * 2];
#pragma unroll
                for (int tn = 0; tn < 8; tn++) {
                    mx = fmaxf(mx, S[tm][tn][rh * 2 + 0]);
                    mx = fmaxf(mx, S[tm][tn][rh * 2 + 1]);
                }
                mx = fmaxf(mx, __shfl_xor_sync(0xffffffffu, mx, 1));
                mx = fmaxf(mx, __shfl_xor_sync(0xffffffffu, mx, 2));
                float mold = mrow[tm][rh];
                float mnew = fmaxf(mold, mx);
                float corr = ex2f(mold - mnew);
                mrow[tm][rh] = mnew;
                float rsum = 0.f;
#pragma unroll
                for (int tn = 0; tn < 8; tn++) {
                    float p0 = ex2f(S[tm][tn][rh * 2 + 0] - mnew);
                    float p1 = ex2f(S[tm][tn][rh * 2 + 1] - mnew);
                    rsum += p0 + p1;
                    float h0 = __bfloat162float(__float2bfloat16(p0));
                    float h1 = __bfloat162float(__float2bfloat16(p1));
                    Ppk[tm][0][tn * 2 + rh] = packbf2(p0, p1);
                    Ppk[tm][1][tn * 2 + rh] = packbf2(p0 - h0, p1 - h1);
                    O[tm][tn][rh * 2 + 0] *= corr;
                    O[tm][tn][rh * 2 + 1] *= corr;
                }
                rsum += __shfl_xor_sync(0xffffffffu, rsum, 1);
                rsum += __shfl_xor_sync(0xffffffffu, rsum, 2);
                lrow[tm][rh] = lrow[tm][rh] * corr + rsum;
            }
        }

        // ---- PV phase A: V_hi with P_hi and P_lo ----
#pragma unroll
        for (int kk = 0; kk < 4; kk++) {
            uint32_t bfv[4][4];
#pragma unroll
            for (int p = 0; p < 4; p++) {
                int row = p * 16 + (lane & 7) + (lane >> 4) * 8;
                int chunk = kk * 2 + ((lane >> 3) & 1);
                ldsm4(bfv[p], sV[b] + swz128(row, chunk));
            }
#pragma unroll
            for (int tm = 0; tm < 2; tm++)
#pragma unroll
                for (int tn = 0; tn < 8; tn++) {
                    const uint32_t* bb = &bfv[tn >> 1][(tn & 1) * 2];
                    mma_bf16(O[tm][tn], &Ppk[tm][0][4 * kk], bb);
                    mma_bf16(O[tm][tn], &Ppk[tm][1][4 * kk], bb);
                }
        }
        // ---- PV phase B: V_lo with P_hi ----
#pragma unroll
        for (int kk = 0; kk < 4; kk++) {
            uint32_t bfv[4][4];
#pragma unroll
            for (int p = 0; p < 4; p++) {
                int row = 64 + p * 16 + (lane & 7) + (lane >> 4) * 8;
                int chunk = kk * 2 + ((lane >> 3) & 1);
                ldsm4(bfv[p], sV[b] + swz128(row, chunk));
            }
#pragma unroll
            for (int tm = 0; tm < 2; tm++)
#pragma unroll
                for (int tn = 0; tn < 8; tn++)
                    mma_bf16(O[tm][tn], &Ppk[tm][0][4 * kk],
                             &bfv[tn >> 1][(tn & 1) * 2]);
        }
        __syncthreads();
    }

    // ---- epilogue: write split ctx [hi|lo] into A2 ----
    const int bb = bh >> 4, h = bh & 15;
#pragma unroll
    for (int tm = 0; tm < 2; tm++) {
#pragma unroll
        for (int rh = 0; rh < 2; rh++) {
            float inv = 1.f / lrow[tm][rh];
            int trow = qtile * AQ + wid * 32 + tm * 16 + rh * 8 + (lane >> 2);
            size_t m = (size_t)bb * TSEQ + trow;
            __nv_bfloat16* rowp = A2 + m * KROW + h * 64;
#pragma unroll
            for (int tn = 0; tn < 8; tn++) {
                float o0 = O[tm][tn][rh * 2 + 0] * inv;
                float o1 = O[tm][tn][rh * 2 + 1] * inv;
                int d = tn * 8 + (lane & 3) * 2;
                uint32_t hi2 = packbf2(o0, o1);
                float h0 = __bfloat162float(__float2bfloat16(o0));
                float h1 = __bfloat162float(__float2bfloat16(o1));
                uint32_t lo2 = packbf2(o0 - h0, o1 - h1);
                *(uint32_t*)(rowp + d) = hi2;
                *(uint32_t*)(rowp + 1024 + d) = lo2;
            }
        }
    }
}

// ---------------------------------------------------------------------------
// Launch
// ---------------------------------------------------------------------------
extern "C" void kernel_launch(void* const* d_in, const int* in_sizes, int n_in,
                              void* d_out, int out_size)
{
    const float* x  = (const float*)d_in[0];
    const float* Wq = (const float*)d_in[1];
    const float* bq = (const float*)d_in[2];
    const float* Wk = (const float*)d_in[3];
    const float* bk = (const float*)d_in[4];
    const float* Wv = (const float*)d_in[5];
    const float* bv = (const float*)d_in[6];
    const float* Wo = (const float*)d_in[7];
    const float* bo = (const float*)d_in[8];
    float* out = (float*)d_out;

    float *Qp, *Kp, *Vp, *BIp;
    __nv_bfloat16 *A2p, *Bqkvp, *Bop, *Qhp, *Khp, *Vtp;
    cudaGetSymbolAddress((void**)&Qp, g_Q);
    cudaGetSymbolAddress((void**)&Kp, g_K);
    cudaGetSymbolAddress((void**)&Vp, g_V);
    cudaGetSymbolAddress((void**)&A2p, g_A2);
    cudaGetSymbolAddress((void**)&Bqkvp, g_Bqkv);
    cudaGetSymbolAddress((void**)&Bop, g_Bo);
    cudaGetSymbolAddress((void**)&BIp, g_bias_qkv);
    cudaGetSymbolAddress((void**)&Qhp, g_Qh);
    cudaGetSymbolAddress((void**)&Khp, g_Kh);
    cudaGetSymbolAddress((void**)&Vtp, g_Vt);

    cudaFuncSetAttribute(attn_mma, cudaFuncAttributeMaxDynamicSharedMemorySize, ATTN_SMEM);
    cudaFuncSetAttribute(gemm_hmma, cudaFuncAttributeMaxDynamicSharedMemorySize, GEMM_SMEM);

    // trig table + fused split conversions (+ bias concat tail blocks)
    trig_kernel<<<TSEQ * 32 / 256, 256>>>();
    split_all<<<32768 + 12, 256>>>(x, Wq, Wk, Wv, Wo, bq, bk, bv, A2p, Bqkvp, Bop);

    // fused QKV projection -> fp32 [B,H,T,Dh]
    gemm_hmma<<<dim3(3072 / 128, MROWS / 128), 256, GEMM_SMEM>>>(
        A2p, Bqkvp, BIp, nullptr, Qp, Kp, Vp, 1);

    // RoPE + bf16 split conversions (table-based)
    rope_convert<<<(BHTOT * TSEQ * 32) / 256, 256>>>(Qp, Kp, Qhp, Khp);
    v_convert<<<dim3(TSEQ / 64, BHTOT), 256>>>(Vp, Vtp);

    // HMMA flash attention -> split ctx in g_A2
    attn_mma<<<dim3(TSEQ / AQ, BHTOT), 128, ATTN_SMEM>>>(Qhp, Khp, Vtp, A2p);

    // output projection -> d_out
    gemm_hmma<<<dim3(1024 / 128, MROWS / 128), 256, GEMM_SMEM>>>(
        A2p, Bop, bo, out, nullptr, nullptr, nullptr, 0);

    (void)in_sizes; (void)n_in; (void)out_size;
}

// round 11
// speedup vs baseline: 4.0381x; 1.0271x over previous
#include <cuda_runtime.h>
#include <cuda_bf16.h>
#include <math.h>
#include <stdint.h>

// Problem constants
#define BATCH  2
#define TSEQ   2048
#define DMODEL 1024
#define NHEADS 16
#define HDIM   64
#define BHTOT  (BATCH * NHEADS)     // 32
#define MROWS  (BATCH * TSEQ)       // 4096
#define KROW   2048                 // hi|lo row stride (bf16)

// ---------------------------------------------------------------------------
// Scratch
// ---------------------------------------------------------------------------
__device__ float g_V[BHTOT * TSEQ * HDIM];                  // [B,H,T,Dh] fp32
__device__ __nv_bfloat16 g_Qh[(size_t)BHTOT * TSEQ * 128];  // [bh][t][hi64|lo64]
__device__ __nv_bfloat16 g_Kh[(size_t)BHTOT * TSEQ * 128];
__device__ __nv_bfloat16 g_Vt[(size_t)BHTOT * 128 * TSEQ];  // [bh][d'128][t]
__device__ __nv_bfloat16 g_A2[(size_t)MROWS * KROW];      // split activations [hi|lo]
__device__ __nv_bfloat16 g_Bqkv[(size_t)3072 * KROW];     // split Wq|Wk|Wv [hi|lo]
__device__ __nv_bfloat16 g_Bo[(size_t)1024 * KROW];       // split Wo [hi|lo]
__device__ float g_bias_qkv[3072];
__device__ float2 g_trig[TSEQ * 32];                      // cos/sin table [t][d]

// ---------------------------------------------------------------------------
// Helpers
// ---------------------------------------------------------------------------
__device__ __forceinline__ uint32_t smem_u32(const void* p) {
    uint32_t a;
    asm("{ .reg .u64 t; cvta.to.shared.u64 t, %1; cvt.u32.u64 %0, t; }"
        : "=r"(a) : "l"(p));
    return a;
}

#define CP_ASYNC16(sm, gp) \
    asm volatile("cp.async.cg.shared.global [%0], [%1], 16;" :: "r"((uint32_t)(sm)), "l"(gp) : "memory")
#define CP_COMMIT() asm volatile("cp.async.commit_group;" ::: "memory")
#define CP_WAIT(n)  asm volatile("cp.async.wait_group %0;" :: "n"(n) : "memory")

__device__ __forceinline__ void ldsm4(uint32_t* r, uint32_t addr) {
    asm volatile("ldmatrix.sync.aligned.m8n8.x4.shared.b16 {%0,%1,%2,%3}, [%4];"
        : "=r"(r[0]), "=r"(r[1]), "=r"(r[2]), "=r"(r[3]) : "r"(addr));
}

__device__ __forceinline__ void mma_bf16(float* c, const uint32_t* a, const uint32_t* b) {
    asm volatile(
        "mma.sync.aligned.m16n8k16.row.col.f32.bf16.bf16.f32 "
        "{%0,%1,%2,%3}, {%4,%5,%6,%7}, {%8,%9}, {%0,%1,%2,%3};"
        : "+f"(c[0]), "+f"(c[1]), "+f"(c[2]), "+f"(c[3])
        : "r"(a[0]), "r"(a[1]), "r"(a[2]), "r"(a[3]), "r"(b[0]), "r"(b[1]));
}

__device__ __forceinline__ float ex2f(float x) {
    float r; asm("ex2.approx.f32 %0, %1;" : "=f"(r) : "f"(x)); return r;
}

__device__ __forceinline__ uint32_t packbf2(float a, float b) {
    uint32_t r; asm("cvt.rn.bf16x2.f32 %0, %1, %2;" : "=r"(r) : "f"(b), "f"(a)); return r;
}

// swizzles: 16B-chunk XOR within a row
__device__ __forceinline__ uint32_t swz256(int row, int chunk) {     // 256B rows
    return (uint32_t)(row * 256 + ((chunk ^ (row & 7)) << 4));
}
__device__ __forceinline__ uint32_t swz128(int row, int chunk) {     // 128B rows
    return (uint32_t)(row * 128 + ((chunk ^ (row & 7)) << 4));
}

#define QSCALE (0.125f * 1.44269504088896340736f)

// ---------------------------------------------------------------------------
// trig table: g_trig[t*32+d] = (cos, sin)(t * 10000^{-d/32})
// ---------------------------------------------------------------------------
__global__ void trig_kernel()
{
    int idx = blockIdx.x * blockDim.x + threadIdx.x;   // 65536
    int t = idx >> 5, d = idx & 31;
    float inv_freq = powf(10000.f, -(float)d * (1.f / 32.f));
    float s, c;
    sincosf((float)t * inv_freq, &s, &c);
    g_trig[idx] = make_float2(c, s);
}

// ---------------------------------------------------------------------------
// Fused split: x, Wq, Wk, Wv, Wo -> [hi|lo] bf16 layouts, + bias concat tail.
// ---------------------------------------------------------------------------
__global__ void split_all(const float* __restrict__ x,
                          const float* __restrict__ Wq, const float* __restrict__ Wk,
                          const float* __restrict__ Wv, const float* __restrict__ Wo,
                          const float* __restrict__ bq, const float* __restrict__ bk,
                          const float* __restrict__ bv,
                          __nv_bfloat16* __restrict__ A2,
                          __nv_bfloat16* __restrict__ Bqkv,
                          __nv_bfloat16* __restrict__ Bo)
{
    int bid = blockIdx.x;
    int tid = threadIdx.x;
    if (bid >= 32768) {                       // bias tail: 12 blocks x 256 = 3072
        int i = (bid - 32768) * 256 + tid;
        const float* s = (i < 1024) ? bq : ((i < 2048) ? bk : bv);
        g_bias_qkv[i] = s[i & 1023];
        return;
    }
    int idx = bid * 256 + tid;
    int row = idx >> 10, k = idx & 1023;
    const float* src;
    __nv_bfloat16* dst;
    int lrow;
    if (row < 4096)      { src = x;  dst = A2;                          lrow = row; }
    else if (row < 5120) { src = Wq; dst = Bqkv;                        lrow = row - 4096; }
    else if (row < 6144) { src = Wk; dst = Bqkv + (size_t)1024 * KROW;  lrow = row - 5120; }
    else if (row < 7168) { src = Wv; dst = Bqkv + (size_t)2048 * KROW;  lrow = row - 6144; }
    else                 { src = Wo; dst = Bo;                          lrow = row - 7168; }
    float v = src[(size_t)lrow * 1024 + k];
    __nv_bfloat16 hi = __float2bfloat16(v);
    __nv_bfloat16 lo = __float2bfloat16(v - __bfloat162float(hi));
    size_t base = (size_t)lrow * KROW;
    dst[base + k] = hi;
    dst[base + 1024 + k] = lo;
}

// ---------------------------------------------------------------------------
// HMMA bf16 GEMM: C = x @ W^T + bias via 3-term split over [hi|lo] layout.
// mode 0: fp32 row-major out.
// mode 1: QKV — Q/K thirds get RoPE+scale applied IN REGISTERS and are
//         written as bf16 [hi|lo] to g_Qh/g_Kh; V third -> fp32 g_V.
// ---------------------------------------------------------------------------
#define GNS 48
#define GSTG 3
#define GEMM_SMEM (GSTG * 2 * 128 * 128)   // 98304

__global__ __launch_bounds__(256, 2) void gemm_hmma(
    const __nv_bfloat16* __restrict__ A2, const __nv_bfloat16* __restrict__ B2,
    const float* __restrict__ bias, float* __restrict__ out0,
    float* __restrict__ outV, int mode)
{
    extern __shared__ __align__(128) char gsm[];
    const uint32_t base = smem_u32(gsm);

    const int tid = threadIdx.x;
    const int lane = tid & 31;
    const int wid = tid >> 5;
    const int warp_m = wid & 3;
    const int warp_n = wid >> 2;
    const int m0 = blockIdx.y * 128;
    const int n0 = blockIdx.x * 128;

    uint32_t sbA[GSTG], sbB[GSTG];
#pragma unroll
    for (int i = 0; i < GSTG; i++) {
        sbA[i] = base + i * 32768;
        sbB[i] = base + i * 32768 + 16384;
    }

    const __nv_bfloat16* Abase = A2 + (size_t)m0 * KROW;
    const __nv_bfloat16* Bbase = B2 + (size_t)n0 * KROW;

    float acc[2][8][4];
#pragma unroll
    for (int i = 0; i < 2; i++)
#pragma unroll
        for (int j = 0; j < 8; j++)
#pragma unroll
            for (int q = 0; q < 4; q++) acc[i][j][q] = 0.f;

    auto load_stage = [&](int s) {
        int b = s % GSTG;
        int term = s >> 4, sub = s & 15;
        int aoff = ((term == 1) ? 1024 : 0) + sub * 64;
        int boff = ((term == 2) ? 1024 : 0) + sub * 64;
        const __nv_bfloat16* Ag = Abase + aoff;
        const __nv_bfloat16* Bg = Bbase + boff;
#pragma unroll
        for (int u = 0; u < 4; u++) {
            int flat = tid + u * 256;            // 0..1023
            int r = flat >> 3, c = flat & 7;
            uint32_t off = swz128(r, c);
            CP_ASYNC16(sbA[b] + off, (const void*)(Ag + (size_t)r * KROW + c * 8));
            CP_ASYNC16(sbB[b] + off, (const void*)(Bg + (size_t)r * KROW + c * 8));
        }
        CP_COMMIT();
    };

    load_stage(0);
    load_stage(1);

    for (int s = 0; s < GNS; s++) {
        int b = s % GSTG;
        if (s < GNS - 1) { CP_WAIT(1); } else { CP_WAIT(0); }
        __syncthreads();

#pragma unroll
        for (int kk = 0; kk < 4; kk++) {
            uint32_t af[2][4];
#pragma unroll
            for (int tm = 0; tm < 2; tm++) {
                int row = warp_m * 32 + tm * 16 + (lane & 7) + ((lane >> 3) & 1) * 8;
                int chunk = kk * 2 + (lane >> 4);
                ldsm4(af[tm], sbA[b] + swz128(row, chunk));
            }
            uint32_t bf[4][4];
#pragma unroll
            for (int p = 0; p < 4; p++) {
                int row = warp_n * 64 + p * 16 + (lane & 7) + (lane >> 4) * 8;
                int chunk = kk * 2 + ((lane >> 3) & 1);
                ldsm4(bf[p], sbB[b] + swz128(row, chunk));
            }
#pragma unroll
            for (int tm = 0; tm < 2; tm++)
#pragma unroll
                for (int tn = 0; tn < 8; tn++)
                    mma_bf16(acc[tm][tn], af[tm], &bf[tn >> 1][(tn & 1) * 2]);
        }

        if (s + 2 < GNS) load_stage(s + 2);
    }

    const int m_base = m0 + warp_m * 32;
    const int n_base = n0 + warp_n * 64;

    if (mode == 0) {
#pragma unroll
        for (int tm = 0; tm < 2; tm++) {
#pragma unroll
            for (int tn = 0; tn < 8; tn++) {
                int r0 = m_base + tm * 16 + (lane >> 2);
                int c0 = n_base + tn * 8 + 2 * (lane & 3);
                float bx = bias[c0], by = bias[c0 + 1];
#pragma unroll
                for (int half = 0; half < 2; half++) {
                    int m = r0 + half * 8;
                    float2* dst = (float2*)(out0 + (size_t)m * 1024 + c0);
                    *dst = make_float2(acc[tm][tn][half * 2 + 0] + bx,
                                       acc[tm][tn][half * 2 + 1] + by);
                }
            }
        }
        return;
    }

    // mode 1: which third (Q/K/V) — constant per warp (64-col span = 1 head)
    const int which = n_base >> 10;
    const int head = (n_base & 1023) >> 6;

    if (which == 2) {
        // V: fp32 scatter to [B,H,T,Dh]
#pragma unroll
        for (int tm = 0; tm < 2; tm++) {
#pragma unroll
            for (int tn = 0; tn < 8; tn++) {
                int r0 = m_base + tm * 16 + (lane >> 2);
                int c0 = n_base + tn * 8 + 2 * (lane & 3);
                float bx = bias[c0], by = bias[c0 + 1];
                int d0 = c0 & 63;
#pragma unroll
                for (int half = 0; half < 2; half++) {
                    int m = r0 + half * 8;
                    int bb2 = m >> 11;
                    int t = m & (TSEQ - 1);
                    float2* dst = (float2*)(outV +
                        (((size_t)(bb2 * NHEADS + head)) * TSEQ + t) * HDIM + d0);
                    *dst = make_float2(acc[tm][tn][half * 2 + 0] + bx,
                                       acc[tm][tn][half * 2 + 1] + by);
                }
            }
        }
    } else {
        // Q or K: fused RoPE (+QSCALE for Q) + bf16 hi/lo split
        __nv_bfloat16* dstb = (which == 0) ? g_Qh : g_Kh;
        const float scale = (which == 0) ? QSCALE : 1.f;
#pragma unroll
        for (int tm = 0; tm < 2; tm++) {
#pragma unroll
            for (int tn = 0; tn < 4; tn++) {
                int c0 = n_base + tn * 8 + 2 * (lane & 3);
                int d = c0 & 31;                     // even, partner at d+32
                float b1x = bias[c0],      b1y = bias[c0 + 1];
                float b2x = bias[c0 + 32], b2y = bias[c0 + 33];
#pragma unroll
                for (int half = 0; half < 2; half++) {
                    int m = m_base + tm * 16 + (lane >> 2) + half * 8;
                    int bb2 = m >> 11;
                    int t = m & (TSEQ - 1);
                    float2 cs0 = g_trig[(t << 5) + d];
                    float2 cs1 = g_trig[(t << 5) + d + 1];
                    float q1x = acc[tm][tn][half * 2 + 0] + b1x;
                    float q1y = acc[tm][tn][half * 2 + 1] + b1y;
                    float q2x = acc[tm][tn + 4][half * 2 + 0] + b2x;
                    float q2y = acc[tm][tn + 4][half * 2 + 1] + b2y;
                    float o1x = (q1x * cs0.x - q2x * cs0.y) * scale;
                    float o2x = (q2x * cs0.x + q1x * cs0.y) * scale;
                    float o1y = (q1y * cs1.x - q2y * cs1.y) * scale;
                    float o2y = (q2y * cs1.x + q1y * cs1.y) * scale;
                    // split hi/lo
                    float h1x = __bfloat162float(__float2bfloat16(o1x));
                    float h1y = __bfloat162float(__float2bfloat16(o1y));
                    float h2x = __bfloat162float(__float2bfloat16(o2x));
                    float h2y = __bfloat162float(__float2bfloat16(o2y));
                    size_t ob = (((size_t)(bb2 * NHEADS + head)) * TSEQ + t) * 128;
                    *(uint32_t*)(dstb + ob + d)      = packbf2(o1x, o1y);
                    *(uint32_t*)(dstb + ob + 32 + d) = packbf2(o2x, o2y);
                    *(uint32_t*)(dstb + ob + 64 + d) = packbf2(o1x - h1x, o1y - h1y);
                    *(uint32_t*)(dstb + ob + 96 + d) = packbf2(o2x - h2x, o2y - h2y);
                }
            }
        }
    }
}

// ---------------------------------------------------------------------------
// V transpose + split
// ---------------------------------------------------------------------------
__global__ void v_convert(const float* __restrict__ V, __nv_bfloat16* __restrict__ Vt)
{
    __shared__ float tile[64][65];
    int bh = blockIdx.y;
    int t0 = blockIdx.x * 64;
    int tid = threadIdx.x;   // 256
#pragma unroll
    for (int i = 0; i < 16; i++) {
        int flat = tid + i * 256;
        int r = flat >> 6, d = flat & 63;
        tile[r][d] = V[((size_t)bh * TSEQ + t0 + r) * HDIM + d];
    }
    __syncthreads();
#pragma unroll
    for (int i = 0; i < 16; i++) {
        int flat = tid + i * 256;
        int d = flat >> 6, c = flat & 63;
        float v = tile[c][d];
        __nv_bfloat16 h = __float2bfloat16(v);
        Vt[((size_t)bh * 128 + d) * TSEQ + t0 + c] = h;
        Vt[((size_t)bh * 128 + 64 + d) * TSEQ + t0 + c] =
            __float2bfloat16(v - __bfloat162float(h));
    }
}

// ---------------------------------------------------------------------------
// HMMA flash attention with fragment-reuse term scheduling (unchanged).
// ---------------------------------------------------------------------------
#define AQ 128
#define AK 64
#define NKT (TSEQ / AK)   // 32
#define ATTN_SMEM 98304

__global__ __launch_bounds__(128) void attn_mma(
    const __nv_bfloat16* __restrict__ Qh, const __nv_bfloat16* __restrict__ Kh,
    const __nv_bfloat16* __restrict__ Vt, __nv_bfloat16* __restrict__ A2)
{
    extern __shared__ __align__(128) char smem[];
    const uint32_t sQ = smem_u32(smem);
    const uint32_t sK[2] = { sQ + 32768, sQ + 32768 + 16384 };
    const uint32_t sV[2] = { sQ + 65536, sQ + 65536 + 16384 };

    const int tid = threadIdx.x, lane = tid & 31, wid = tid >> 5;
    const int qtile = blockIdx.x, bh = blockIdx.y;

    const __nv_bfloat16* Qg = Qh + ((size_t)bh * TSEQ + qtile * AQ) * 128;
    const __nv_bfloat16* Kg = Kh + (size_t)bh * TSEQ * 128;
    const __nv_bfloat16* Vg = Vt + (size_t)bh * 128 * TSEQ;

    auto loadKV = [&](int t) {
        int b = t & 1;
        const __nv_bfloat16* Kt = Kg + (size_t)t * AK * 128;
#pragma unroll
        for (int u = 0; u < 8; u++) {
            int flat = tid + u * 128;
            int r = flat >> 4, c = flat & 15;
            CP_ASYNC16(sK[b] + swz256(r, c), (const void*)(Kt + r * 128 + c * 8));
        }
        const __nv_bfloat16* Vtt = Vg + t * AK;
#pragma unroll
        for (int u = 0; u < 8; u++) {
            int flat = tid + u * 128;
            int r = flat >> 3, c = flat & 7;
            CP_ASYNC16(sV[b] + swz128(r, c), (const void*)(Vtt + (size_t)r * TSEQ + c * 8));
        }
    };

#pragma unroll
    for (int u = 0; u < 16; u++) {
        int flat = tid + u * 128;
        int r = flat >> 4, c = flat & 15;
        CP_ASYNC16(sQ + swz256(r, c), (const void*)(Qg + r * 128 + c * 8));
    }
    loadKV(0);
    CP_COMMIT();

    float O[2][8][4];
#pragma unroll
    for (int i = 0; i < 2; i++)
#pragma unroll
        for (int j = 0; j < 8; j++)
#pragma unroll
            for (int q = 0; q < 4; q++) O[i][j][q] = 0.f;
    float mrow[2][2] = { {-1e30f, -1e30f}, {-1e30f, -1e30f} };
    float lrow[2][2] = { {0.f, 0.f}, {0.f, 0.f} };

    for (int t = 0; t < NKT; t++) {
        int b = t & 1;
        if (t + 1 < NKT) { loadKV(t + 1); CP_COMMIT(); CP_WAIT(1); }
        else { CP_WAIT(0); }
        __syncthreads();

        float S[2][8][4];
#pragma unroll
        for (int i = 0; i < 2; i++)
#pragma unroll
            for (int j = 0; j < 8; j++)
#pragma unroll
                for (int q = 0; q < 4; q++) S[i][j][q] = 0.f;

        // ---- QK phase A: K_hi with Q_hi and Q_lo ----
#pragma unroll
        for (int kk = 0; kk < 4; kk++) {
            uint32_t bf4[4][4];
#pragma unroll
            for (int p = 0; p < 4; p++) {
                int row = p * 16 + (lane & 7) + (lane >> 4) * 8;
                int chunk = kk * 2 + ((lane >> 3) & 1);
                ldsm4(bf4[p], sK[b] + swz256(row, chunk));
            }
            uint32_t afh[2][4], afl[2][4];
#pragma unroll
            for (int tm = 0; tm < 2; tm++) {
                int row = wid * 32 + tm * 16 + (lane & 7) + ((lane >> 3) & 1) * 8;
                int chunk = kk * 2 + (lane >> 4);
                ldsm4(afh[tm], sQ + swz256(row, chunk));
                ldsm4(afl[tm], sQ + swz256(row, 8 + chunk));
            }
#pragma unroll
            for (int tm = 0; tm < 2; tm++)
#pragma unroll
                for (int tn = 0; tn < 8; tn++) {
                    const uint32_t* bb = &bf4[tn >> 1][(tn & 1) * 2];
                    mma_bf16(S[tm][tn], afh[tm], bb);
                    mma_bf16(S[tm][tn], afl[tm], bb);
                }
        }
        // ---- QK phase B: K_lo with Q_hi ----
#pragma unroll
        for (int kk = 0; kk < 4; kk++) {
            uint32_t bf4[4][4];
#pragma unroll
            for (int p = 0; p < 4; p++) {
                int row = p * 16 + (lane & 7) + (lane >> 4) * 8;
                int chunk = 8 + kk * 2 + ((lane >> 3) & 1);
                ldsm4(bf4[p], sK[b] + swz256(row, chunk));
            }
            uint32_t afh[2][4];
#pragma unroll
            for (int tm = 0; tm < 2; tm++) {
                int row = wid * 32 + tm * 16 + (lane & 7) + ((lane >> 3) & 1) * 8;
                int chunk = kk * 2 + (lane >> 4);
                ldsm4(afh[tm], sQ + swz256(row, chunk));
            }
#pragma unroll
            for (int tm = 0; tm < 2; tm++)
#pragma unroll
                for (int tn = 0; tn < 8; tn++)
                    mma_bf16(S[tm][tn], afh[tm], &bf4[tn >> 1][(tn & 1) * 2]);
        }

        // ---- online softmax (exp2 domain) + P pack ----
        uint32_t Ppk[2][2][16];
#pragma unroll
        for (int tm = 0; tm < 2; tm++) {
#pragma unroll
            for (int rh = 0; rh < 2; rh++) {
                float mx = S[tm][0][rh * 2];
#pragma unroll
                for (int tn = 0; tn < 8; tn++) {
                    mx = fmaxf(mx, S[tm][tn][rh * 2 + 0]);
                    mx = fmaxf(mx, S[tm][tn][rh * 2 + 1]);
                }
                mx = fmaxf(mx, __shfl_xor_sync(0xffffffffu, mx, 1));
                mx = fmaxf(mx, __shfl_xor_sync(0xffffffffu, mx, 2));
                float mold = mrow[tm][rh];
                float mnew = fmaxf(mold, mx);
                float corr = ex2f(mold - mnew);
                mrow[tm][rh] = mnew;
                float rsum = 0.f;
#pragma unroll
                for (int tn = 0; tn < 8; tn++) {
                    float p0 = ex2f(S[tm][tn][rh * 2 + 0] - mnew);
                    float p1 = ex2f(S[tm][tn][rh * 2 + 1] - mnew);
                    rsum += p0 + p1;
                    float h0 = __bfloat162float(__float2bfloat16(p0));
                    float h1 = __bfloat162float(__float2bfloat16(p1));
                    Ppk[tm][0][tn * 2 + rh] = packbf2(p0, p1);
                    Ppk[tm][1][tn * 2 + rh] = packbf2(p0 - h0, p1 - h1);
                    O[tm][tn][rh * 2 + 0] *= corr;
                    O[tm][tn][rh * 2 + 1] *= corr;
                }
                rsum += __shfl_xor_sync(0xffffffffu, rsum, 1);
                rsum += __shfl_xor_sync(0xffffffffu, rsum, 2);
                lrow[tm][rh] = lrow[tm][rh] * corr + rsum;
            }
        }

        // ---- PV phase A: V_hi with P_hi and P_lo ----
#pragma unroll
        for (int kk = 0; kk < 4; kk++) {
            uint32_t bfv[4][4];
#pragma unroll
            for (int p = 0; p < 4; p++) {
                int row = p * 16 + (lane & 7) + (lane >> 4) * 8;
                int chunk = kk * 2 + ((lane >> 3) & 1);
                ldsm4(bfv[p], sV[b] + swz128(row, chunk));
            }
#pragma unroll
            for (int tm = 0; tm < 2; tm++)
#pragma unroll
                for (int tn = 0; tn < 8; tn++) {
                    const uint32_t* bb = &bfv[tn >> 1][(tn & 1) * 2];
                    mma_bf16(O[tm][tn], &Ppk[tm][0][4 * kk], bb);
                    mma_bf16(O[tm][tn], &Ppk[tm][1][4 * kk], bb);
                }
        }
        // ---- PV phase B: V_lo with P_hi ----
#pragma unroll
        for (int kk = 0; kk < 4; kk++) {
            uint32_t bfv[4][4];
#pragma unroll
            for (int p = 0; p < 4; p++) {
                int row = 64 + p * 16 + (lane & 7) + (lane >> 4) * 8;
                int chunk = kk * 2 + ((lane >> 3) & 1);
                ldsm4(bfv[p], sV[b] + swz128(row, chunk));
            }
#pragma unroll
            for (int tm = 0; tm < 2; tm++)
#pragma unroll
                for (int tn = 0; tn < 8; tn++)
                    mma_bf16(O[tm][tn], &Ppk[tm][0][4 * kk],
                             &bfv[tn >> 1][(tn & 1) * 2]);
        }
        __syncthreads();
    }

    // ---- epilogue: write split ctx [hi|lo] into A2 ----
    const int bb = bh >> 4, h = bh & 15;
#pragma unroll
    for (int tm = 0; tm < 2; tm++) {
#pragma unroll
        for (int rh = 0; rh < 2; rh++) {
            float inv = 1.f / lrow[tm][rh];
            int trow = qtile * AQ + wid * 32 + tm * 16 + rh * 8 + (lane >> 2);
            size_t m = (size_t)bb * TSEQ + trow;
            __nv_bfloat16* rowp = A2 + m * KROW + h * 64;
#pragma unroll
            for (int tn = 0; tn < 8; tn++) {
                float o0 = O[tm][tn][rh * 2 + 0] * inv;
                float o1 = O[tm][tn][rh * 2 + 1] * inv;
                int d = tn * 8 + (lane & 3) * 2;
                uint32_t hi2 = packbf2(o0, o1);
                float h0 = __bfloat162float(__float2bfloat16(o0));
                float h1 = __bfloat162float(__float2bfloat16(o1));
                uint32_t lo2 = packbf2(o0 - h0, o1 - h1);
                *(uint32_t*)(rowp + d) = hi2;
                *(uint32_t*)(rowp + 1024 + d) = lo2;
            }
        }
    }
}

// ---------------------------------------------------------------------------
// Launch
// ---------------------------------------------------------------------------
extern "C" void kernel_launch(void* const* d_in, const int* in_sizes, int n_in,
                              void* d_out, int out_size)
{
    const float* x  = (const float*)d_in[0];
    const float* Wq = (const float*)d_in[1];
    const float* bq = (const float*)d_in[2];
    const float* Wk = (const float*)d_in[3];
    const float* bk = (const float*)d_in[4];
    const float* Wv = (const float*)d_in[5];
    const float* bv = (const float*)d_in[6];
    const float* Wo = (const float*)d_in[7];
    const float* bo = (const float*)d_in[8];
    float* out = (float*)d_out;

    float *Vp, *BIp;
    __nv_bfloat16 *A2p, *Bqkvp, *Bop, *Qhp, *Khp, *Vtp;
    cudaGetSymbolAddress((void**)&Vp, g_V);
    cudaGetSymbolAddress((void**)&A2p, g_A2);
    cudaGetSymbolAddress((void**)&Bqkvp, g_Bqkv);
    cudaGetSymbolAddress((void**)&Bop, g_Bo);
    cudaGetSymbolAddress((void**)&BIp, g_bias_qkv);
    cudaGetSymbolAddress((void**)&Qhp, g_Qh);
    cudaGetSymbolAddress((void**)&Khp, g_Kh);
    cudaGetSymbolAddress((void**)&Vtp, g_Vt);

    cudaFuncSetAttribute(attn_mma, cudaFuncAttributeMaxDynamicSharedMemorySize, ATTN_SMEM);
    cudaFuncSetAttribute(gemm_hmma, cudaFuncAttributeMaxDynamicSharedMemorySize, GEMM_SMEM);

    // trig table + fused split conversions (+ bias concat tail blocks)
    trig_kernel<<<TSEQ * 32 / 256, 256>>>();
    split_all<<<32768 + 12, 256>>>(x, Wq, Wk, Wv, Wo, bq, bk, bv, A2p, Bqkvp, Bop);

    // fused QKV projection + RoPE + bf16 split (Q,K) / fp32 (V)
    gemm_hmma<<<dim3(3072 / 128, MROWS / 128), 256, GEMM_SMEM>>>(
        A2p, Bqkvp, BIp, nullptr, Vp, 1);

    // V transpose + split
    v_convert<<<dim3(TSEQ / 64, BHTOT), 256>>>(Vp, Vtp);

    // HMMA flash attention -> split ctx in g_A2
    attn_mma<<<dim3(TSEQ / AQ, BHTOT), 128, ATTN_SMEM>>>(Qhp, Khp, Vtp, A2p);

    // output projection -> d_out
    gemm_hmma<<<dim3(1024 / 128, MROWS / 128), 256, GEMM_SMEM>>>(
        A2p, Bop, bo, out, nullptr, 0);

    (void)in_sizes; (void)n_in; (void)out_size;
}